// round 8
// baseline (speedup 1.0000x reference)
#include <cuda_runtime.h>
#include <cuda_fp16.h>
#include <math.h>

#define NN     128
#define PLANE  16384
#define STRIDE 129            // fp32 plane stride (k_img)
#define STRH   130            // half2 plane stride (k_o1/k_o2)
#define BATCH  64
#define NJ     4
#define NL     4
#define NPAIR  6
#define NTI    1024           // k_img threads
#define NTS    512            // k_o1/k_o2 threads (2 CTAs/SM)

#define SH_PLANE_BYTES (NN * STRH * sizeof(__half2))   // 66560

// ---------------- device scratch ----------------
static __device__ float2 g_ihat [BATCH * PLANE];                 // bitrev order
static __device__ float2 g_u1hat[BATCH * NJ * NL * PLANE];       // bitrev order
static __device__ float  g_psi  [NJ * NL * PLANE];               // bitrev order
static __device__ float  g_s0   [BATCH];
static __device__ float  g_s1p  [BATCH * NJ * NL];
static __device__ float  g_s2p  [BATCH * NPAIR * NL * NL];

__device__ __constant__ int PJ1[NPAIR] = {0,0,0,1,1,2};
__device__ __constant__ int PJ2[NPAIR] = {1,2,3,2,3,3};

// ---------------- helpers ----------------
__device__ __forceinline__ float2 cmulf(float2 a, float2 b) {
    return make_float2(a.x*b.x - a.y*b.y, a.x*b.y + a.y*b.x);
}
__device__ __forceinline__ float2 caddf(float2 a, float2 b){ return make_float2(a.x+b.x, a.y+b.y); }
__device__ __forceinline__ float2 csubf(float2 a, float2 b){ return make_float2(a.x-b.x, a.y-b.y); }

__device__ __forceinline__ void init_tw(float2* tw, int tid) {
    if (tid < 128) {
        float s, c;
        __sincosf(-6.283185307179586f * (float)tid * (1.0f/128.0f), &s, &c);
        tw[tid] = make_float2(c, s);   // W_128^k
    }
}

// fp32 exchange (2 SHFL)
__device__ __forceinline__ float2 shflx(float2 v, int h) {
    float2 o;
    o.x = __shfl_xor_sync(0xffffffffu, v.x, h);
    o.y = __shfl_xor_sync(0xffffffffu, v.y, h);
    return o;
}

// fp16-packed exchange (1 SHFL): partner's copy is fp16-rounded, own copy stays fp32
__device__ __forceinline__ float2 shflx_h(float2 v, int h) {
    __half2 p = __float22half2_rn(v);
    unsigned int pi = *reinterpret_cast<unsigned int*>(&p);
    unsigned int oi = __shfl_xor_sync(0xffffffffu, pi, h);
    __half2 o = *reinterpret_cast<__half2*>(&oi);
    return __half22float2(o);
}

__device__ __forceinline__ float fast_mag(float2 z) {
    float m2 = fmaf(z.x, z.x, z.y * z.y);
    float r;
    asm("sqrt.approx.f32 %0, %1;" : "=f"(r) : "f"(m2));
    return r;
}

// ---------------- 128-pt FFT: 16 lanes x 8 regs, position p = u + 16*i ----------------
// Forward DIF: natural in -> bit-reversed out. H16: fp16-packed shuffles.
template<bool H16>
__device__ __forceinline__ void fft128_fwd(float2 x[8], int u, const float2* __restrict__ tw) {
    #pragma unroll
    for (int qi = 0; qi < 2; ++qi) {
        float2 a = x[qi], b = x[qi+2], c = x[qi+4], d = x[qi+6];
        float2 t3 = caddf(a, c), t1 = csubf(a, c);
        float2 t4 = caddf(b, d), t2 = csubf(b, d);
        int j = u + 16 * qi;
        float2 w1 = tw[j], w2 = tw[2*j], w3 = tw[3*j];
        x[qi]   = caddf(t3, t4);
        x[qi+2] = cmulf(csubf(t3, t4), w2);
        x[qi+4] = cmulf(make_float2(t1.x + t2.y, t1.y - t2.x), w1);
        x[qi+6] = cmulf(make_float2(t1.x - t2.y, t1.y + t2.x), w3);
    }
    {
        float2 w = tw[u << 2];
        #pragma unroll
        for (int i = 0; i < 8; i += 2) {
            float2 a = x[i], b = x[i+1];
            x[i]   = caddf(a, b);
            x[i+1] = cmulf(csubf(a, b), w);
        }
    }
    #pragma unroll
    for (int s = 3; s < 7; ++s) {
        int h = 64 >> s;
        bool lower = (u & h) == 0;
        float sgn = lower ? 1.0f : -1.0f;
        float2 wst = tw[(u & (h - 1)) << s];
        float2 we  = lower ? make_float2(1.0f, 0.0f) : wst;
        #pragma unroll
        for (int i = 0; i < 8; ++i) {
            float2 v = x[i];
            float2 o = H16 ? shflx_h(v, h) : shflx(v, h);
            float2 t = make_float2(fmaf(sgn, v.x, o.x), fmaf(sgn, v.y, o.y));
            x[i] = cmulf(t, we);
        }
    }
}

// Inverse DIT (unnormalized): bit-reversed in -> natural out.
template<bool H16>
__device__ __forceinline__ void fft128_inv(float2 x[8], int u, const float2* __restrict__ tw) {
    #pragma unroll
    for (int s = 6; s >= 3; --s) {
        int h = 64 >> s;
        bool lower = (u & h) == 0;
        float sgn = lower ? 1.0f : -1.0f;
        float2 wst = tw[(u & (h - 1)) << s];
        float2 we  = lower ? make_float2(1.0f, 0.0f) : make_float2(wst.x, -wst.y);
        #pragma unroll
        for (int i = 0; i < 8; ++i) {
            float2 t = cmulf(x[i], we);
            float2 o = H16 ? shflx_h(t, h) : shflx(t, h);
            x[i] = make_float2(fmaf(sgn, t.x, o.x), fmaf(sgn, t.y, o.y));
        }
    }
    {
        float2 w = tw[u << 2]; w.y = -w.y;
        #pragma unroll
        for (int i = 0; i < 8; i += 2) {
            float2 a = x[i], v = cmulf(x[i+1], w);
            x[i]   = caddf(a, v);
            x[i+1] = csubf(a, v);
        }
    }
    #pragma unroll
    for (int qi = 0; qi < 2; ++qi) {
        float2 a = x[qi], b = x[qi+2], c = x[qi+4], d = x[qi+6];
        int j = u + 16 * qi;
        float2 w1 = tw[j],   w2 = tw[2*j],   w3 = tw[3*j];
        w1.y = -w1.y; w2.y = -w2.y; w3.y = -w3.y;
        float2 s1 = cmulf(b, w2);
        float2 s2 = cmulf(c, w1);
        float2 s3 = cmulf(d, w3);
        float2 t3 = caddf(a, s1);
        float2 t4 = csubf(a, s1);
        float2 t1 = caddf(s2, s3);
        float2 t2 = make_float2(s3.y - s2.y, s2.x - s3.x);
        x[qi]   = caddf(t3, t1);
        x[qi+4] = csubf(t3, t1);
        x[qi+2] = caddf(t4, t2);
        x[qi+6] = csubf(t4, t2);
    }
}

// Deterministic block reduction; valid on tid==0. One __syncthreads inside.
template<int NWARPS>
__device__ __forceinline__ float block_sum(float v, float* red, int tid) {
    #pragma unroll
    for (int o = 16; o > 0; o >>= 1) v += __shfl_down_sync(0xffffffffu, v, o);
    if ((tid & 31) == 0) red[tid >> 5] = v;
    __syncthreads();
    float total = 0.0f;
    if (tid == 0) {
        #pragma unroll
        for (int w = 0; w < NWARPS; ++w) total += red[w];
    }
    return total;
}

// ---------------- kernel 1: Morlet bank, pre-permuted to 2D-bitrev ----------------
__global__ void k_psi() {
    int idx = blockIdx.x * blockDim.x + threadIdx.x;
    if (idx >= NJ * NL * PLANE) return;
    int p   = idx >> 14;
    int pos = idx & (PLANE - 1);
    int R = pos >> 7, C = pos & 127;
    int r = __brev((unsigned)R) >> 25;
    int c = __brev((unsigned)C) >> 25;
    int j = p >> 2, l = p & 3;
    float fr = (float)(r < 64 ? r : r - 128) * (6.283185307179586f / 128.0f);
    float fc = (float)(c < 64 ? c : c - 128) * (6.283185307179586f / 128.0f);
    float k0    = 2.356194490192345f / (float)(1 << j);
    float sigma = 0.8f * (float)(1 << j);
    float s2    = sigma * sigma;
    float theta = 0.7853981633974483f * (float)l;
    float k0x = k0 * cosf(theta), k0y = k0 * sinf(theta);
    float beta = expf(-0.5f * s2 * k0 * k0);
    float dx = fr - k0x, dy = fc - k0y;
    float g1 = expf(-0.5f * s2 * (dx*dx + dy*dy));
    float g0 = expf(-0.5f * s2 * (fr*fr + fc*fc));
    g_psi[idx] = g1 - beta * g0;
}

// ---------------- kernel 2: fft2(image) + s0 (fp32 everywhere, 64 blocks) ----------------
__global__ void __launch_bounds__(NTI, 1) k_img(const float* __restrict__ img) {
    extern __shared__ unsigned char smraw[];
    float2* S   = (float2*)smraw;
    float2* tw  = S + NN * STRIDE;
    float*  red = (float*)(tw + 128);
    int b = blockIdx.x, tid = threadIdx.x;
    int u = tid & 15, g = tid >> 4;
    init_tw(tw, tid);
    __syncthreads();
    const float* ip = img + (size_t)b * PLANE;
    float lsum = 0.0f;
    #pragma unroll
    for (int iter = 0; iter < 2; ++iter) {
        int r = g + 64 * iter;
        float2 x[8];
        #pragma unroll
        for (int i = 0; i < 8; ++i) {
            float v = ip[r * NN + u + 16*i];
            lsum += v;
            x[i] = make_float2(v, 0.0f);
        }
        fft128_fwd<false>(x, u, tw);
        #pragma unroll
        for (int i = 0; i < 8; ++i) S[r * STRIDE + u + 16*i] = x[i];
    }
    float tot = block_sum<NTI/32>(lsum, red, tid);
    if (tid == 0) g_s0[b] = tot * (1.0f / 16384.0f);
    #pragma unroll
    for (int iter = 0; iter < 2; ++iter) {
        int c = g + 64 * iter;
        float2 x[8];
        #pragma unroll
        for (int i = 0; i < 8; ++i) x[i] = S[(u + 16*i) * STRIDE + c];
        fft128_fwd<false>(x, u, tw);
        #pragma unroll
        for (int i = 0; i < 8; ++i) S[(u + 16*i) * STRIDE + c] = x[i];
    }
    __syncthreads();
    float2* op = g_ihat + (size_t)b * PLANE;
    for (int i = tid; i < PLANE; i += NTI)
        op[i] = S[(i >> 7) * STRIDE + (i & 127)];
}

// ---------------- kernel 3: order 1 (fp16 shared + fp16 shuffles, 2 CTAs/SM) ----------------
__global__ void __launch_bounds__(NTS, 2) k_o1() {
    extern __shared__ unsigned char smraw[];
    __half2* S  = (__half2*)smraw;
    float2*  tw = (float2*)(smraw + SH_PLANE_BYTES);
    float*   red= (float*)(tw + 128);
    int tid = threadIdx.x;
    int u = tid & 15, hf = (tid >> 4) & 1, w = tid >> 5;
    int rw = (w + (w & 8)) + hf * 8;      // warp rows map, disjoint banks
    int cw = 2 * w + hf;                  // warp cols map, even/odd banks
    int b  = blockIdx.x >> 4;
    int j1 = (blockIdx.x >> 2) & 3;
    int l1 = blockIdx.x & 3;
    init_tw(tw, tid);
    __syncthreads();
    const float2* ih = g_ihat + (size_t)b * PLANE;
    const float*  ps = g_psi + (size_t)(j1 * NL + l1) * PLANE;
    #pragma unroll
    for (int iter = 0; iter < 4; ++iter) {          // fused load*psi + inverse rows
        int r = rw + 32 * iter;
        float2 x[8];
        #pragma unroll
        for (int i = 0; i < 8; ++i) {
            int p = r * NN + u + 16*i;
            float2 v = ih[p];
            float  f = ps[p];
            x[i] = make_float2(v.x * f, v.y * f);
        }
        fft128_inv<true>(x, u, tw);
        #pragma unroll
        for (int i = 0; i < 8; ++i) S[r * STRH + u + 16*i] = __float22half2_rn(x[i]);
    }
    __syncthreads();
    float lsum = 0.0f;
    #pragma unroll
    for (int iter = 0; iter < 4; ++iter) {          // inverse cols -> |.| -> forward cols
        int c = cw + 32 * iter;
        float2 x[8];
        #pragma unroll
        for (int i = 0; i < 8; ++i) x[i] = __half22float2(S[(u + 16*i) * STRH + c]);
        fft128_inv<true>(x, u, tw);
        #pragma unroll
        for (int i = 0; i < 8; ++i) {
            float m = fast_mag(x[i]) * (1.0f / 16384.0f);
            lsum += m;
            x[i] = make_float2(m, 0.0f);
        }
        fft128_fwd<true>(x, u, tw);
        #pragma unroll
        for (int i = 0; i < 8; ++i) S[(u + 16*i) * STRH + c] = __float22half2_rn(x[i]);
    }
    float tot = block_sum<NTS/32>(lsum, red, tid);  // sync inside orders S stores
    if (tid == 0) g_s1p[blockIdx.x] = tot;
    float2* op = g_u1hat + (size_t)blockIdx.x * PLANE;
    #pragma unroll
    for (int iter = 0; iter < 4; ++iter) {          // forward rows, write out from regs
        int r = rw + 32 * iter;
        float2 x[8];
        #pragma unroll
        for (int i = 0; i < 8; ++i) x[i] = __half22float2(S[r * STRH + u + 16*i]);
        fft128_fwd<true>(x, u, tw);
        #pragma unroll
        for (int i = 0; i < 8; ++i) op[r * NN + u + 16*i] = x[i];
    }
}

// ---------------- kernel 4: order 2 (fp16 shared + fp16 shuffles, 2 CTAs/SM) ----------------
__global__ void __launch_bounds__(NTS, 2) k_o2() {
    extern __shared__ unsigned char smraw[];
    __half2* S  = (__half2*)smraw;
    float2*  tw = (float2*)(smraw + SH_PLANE_BYTES);
    float*   red= (float*)(tw + 128);
    int tid = threadIdx.x;
    int u = tid & 15, hf = (tid >> 4) & 1, w = tid >> 5;
    int rw = (w + (w & 8)) + hf * 8;
    int cw = 2 * w + hf;
    int b    = blockIdx.x / 96;
    int rem  = blockIdx.x - b * 96;
    int pair = rem >> 4;
    int l1   = (rem >> 2) & 3;
    int l2   = rem & 3;
    int j1 = PJ1[pair], j2 = PJ2[pair];
    init_tw(tw, tid);
    __syncthreads();
    const float2* uh = g_u1hat + (size_t)(((b * NJ + j1) * NL) + l1) * PLANE;
    const float*  ps = g_psi + (size_t)(j2 * NL + l2) * PLANE;
    #pragma unroll
    for (int iter = 0; iter < 4; ++iter) {          // fused load*psi + inverse rows
        int r = rw + 32 * iter;
        float2 x[8];
        #pragma unroll
        for (int i = 0; i < 8; ++i) {
            int p = r * NN + u + 16*i;
            float2 v = uh[p];
            float  f = ps[p];
            x[i] = make_float2(v.x * f, v.y * f);
        }
        fft128_inv<true>(x, u, tw);
        #pragma unroll
        for (int i = 0; i < 8; ++i) S[r * STRH + u + 16*i] = __float22half2_rn(x[i]);
    }
    __syncthreads();
    float lsum = 0.0f;
    #pragma unroll
    for (int iter = 0; iter < 4; ++iter) {          // inverse cols, |.| from regs
        int c = cw + 32 * iter;
        float2 x[8];
        #pragma unroll
        for (int i = 0; i < 8; ++i) x[i] = __half22float2(S[(u + 16*i) * STRH + c]);
        fft128_inv<true>(x, u, tw);
        #pragma unroll
        for (int i = 0; i < 8; ++i)
            lsum += fast_mag(x[i]);
    }
    float tot = block_sum<NTS/32>(lsum, red, tid);
    if (tid == 0) g_s2p[blockIdx.x] = tot;
}

// ---------------- kernel 5: combine + MLP ----------------
__global__ void k_head(const float* __restrict__ fc1w, const float* __restrict__ fc1b,
                       const float* __restrict__ fc2w, const float* __restrict__ fc2b,
                       float* __restrict__ out) {
    int b = blockIdx.x;
    if (threadIdx.x != 0) return;
    float coeff[11];
    coeff[0] = g_s0[b];
    #pragma unroll
    for (int j = 0; j < 4; ++j) {
        float s = 0.0f;
        #pragma unroll
        for (int l = 0; l < 4; ++l) s += g_s1p[(b * 4 + j) * 4 + l];
        coeff[1 + j] = s * (1.0f / (4.0f * 16384.0f));
    }
    #pragma unroll
    for (int p = 0; p < 6; ++p) {
        float s = 0.0f;
        #pragma unroll
        for (int k = 0; k < 16; ++k) s += g_s2p[(b * 6 + p) * 16 + k];
        coeff[5 + p] = s * (1.0f / 16384.0f) * (1.0f / (16.0f * 16384.0f));
    }
    float h[4];
    #pragma unroll
    for (int k = 0; k < 4; ++k) {
        float a = fc1b[k];
        #pragma unroll
        for (int i = 0; i < 11; ++i) a += coeff[i] * fc1w[k * 11 + i];
        h[k] = fmaxf(a, 0.0f);
    }
    #pragma unroll
    for (int o = 0; o < 10; ++o) {
        float a = fc2b[o];
        #pragma unroll
        for (int k = 0; k < 4; ++k) a += h[k] * fc2w[o * 4 + k];
        out[b * 10 + o] = 1.0f / (1.0f + expf(-a));
    }
}

// ---------------- launch ----------------
extern "C" void kernel_launch(void* const* d_in, const int* in_sizes, int n_in,
                              void* d_out, int out_size) {
    (void)in_sizes; (void)n_in; (void)out_size;
    const float* img  = (const float*)d_in[0];
    const float* fc1w = (const float*)d_in[1];
    const float* fc1b = (const float*)d_in[2];
    const float* fc2w = (const float*)d_in[3];
    const float* fc2b = (const float*)d_in[4];
    float* out = (float*)d_out;

    const size_t SMEM_IMG = (size_t)(NN * STRIDE + 128) * sizeof(float2) + (NTI / 32) * sizeof(float);
    const size_t SMEM_O   = SH_PLANE_BYTES + 128 * sizeof(float2) + (NTS / 32) * sizeof(float);
    cudaFuncSetAttribute(k_img, cudaFuncAttributeMaxDynamicSharedMemorySize, (int)SMEM_IMG);
    cudaFuncSetAttribute(k_o1,  cudaFuncAttributeMaxDynamicSharedMemorySize, (int)SMEM_O);
    cudaFuncSetAttribute(k_o2,  cudaFuncAttributeMaxDynamicSharedMemorySize, (int)SMEM_O);

    k_psi<<<(NJ * NL * PLANE + 255) / 256, 256>>>();
    k_img<<<BATCH, NTI, SMEM_IMG>>>(img);
    k_o1 <<<BATCH * NJ * NL, NTS, SMEM_O>>>();
    k_o2 <<<BATCH * NPAIR * NL * NL, NTS, SMEM_O>>>();
    k_head<<<BATCH, 32>>>(fc1w, fc1b, fc2w, fc2b, out);
}

// round 9
// speedup vs baseline: 1.9364x; 1.9364x over previous
#include <cuda_runtime.h>
#include <cuda_fp16.h>
#include <math.h>

#define NN     128
#define PLANE  16384
#define STRIDE 129            // fp32 plane stride (k_img)
#define STRH   130            // half2 plane stride (k_o1/k_o2)
#define BATCH  64
#define NJ     4
#define NL     4
#define NPAIR  6
#define NTI    1024           // k_img threads
#define NTS    512            // k_o1/k_o2 threads (2 CTAs/SM)

#define SH_PLANE_BYTES (NN * STRH * sizeof(__half2))   // 66560

// ---------------- device scratch ----------------
static __device__ float2 g_ihat [BATCH * PLANE];                 // bitrev order
static __device__ float2 g_u1hat[BATCH * NJ * NL * PLANE];       // bitrev order
static __device__ float  g_psi  [NJ * NL * PLANE];               // bitrev order
static __device__ float  g_s0   [BATCH];
static __device__ float  g_s1p  [BATCH * NJ * NL];
static __device__ float  g_s2p  [BATCH * NPAIR * NL * NL];

__device__ __constant__ int PJ1[NPAIR] = {0,0,0,1,1,2};
__device__ __constant__ int PJ2[NPAIR] = {1,2,3,2,3,3};
// row-frequency support bound per scale j: |kr| <= B (k0 + 5*sigma_f, bins). 64 = full.
__device__ __constant__ int BMAX[NJ] = {64, 64, 44, 22};

// ---------------- helpers ----------------
__device__ __forceinline__ float2 cmulf(float2 a, float2 b) {
    return make_float2(a.x*b.x - a.y*b.y, a.x*b.y + a.y*b.x);
}
__device__ __forceinline__ float2 caddf(float2 a, float2 b){ return make_float2(a.x+b.x, a.y+b.y); }
__device__ __forceinline__ float2 csubf(float2 a, float2 b){ return make_float2(a.x-b.x, a.y-b.y); }

__device__ __forceinline__ void init_tw(float2* tw, int tid) {
    if (tid < 128) {
        float s, c;
        __sincosf(-6.283185307179586f * (float)tid * (1.0f/128.0f), &s, &c);
        tw[tid] = make_float2(c, s);   // W_128^k
    }
}

__device__ __forceinline__ float2 shflx(float2 v, int h) {
    float2 o;
    o.x = __shfl_xor_sync(0xffffffffu, v.x, h);
    o.y = __shfl_xor_sync(0xffffffffu, v.y, h);
    return o;
}

__device__ __forceinline__ float fast_mag(float2 z) {
    float m2 = fmaf(z.x, z.x, z.y * z.y);
    float r;
    asm("sqrt.approx.f32 %0, %1;" : "=f"(r) : "f"(m2));
    return r;
}

// ---------------- 128-pt FFT: 16 lanes x 8 regs, position p = u + 16*i ----------------
// Forward DIF: natural in -> bit-reversed out.
__device__ __forceinline__ void fft128_fwd(float2 x[8], int u, const float2* __restrict__ tw) {
    #pragma unroll
    for (int qi = 0; qi < 2; ++qi) {
        float2 a = x[qi], b = x[qi+2], c = x[qi+4], d = x[qi+6];
        float2 t3 = caddf(a, c), t1 = csubf(a, c);
        float2 t4 = caddf(b, d), t2 = csubf(b, d);
        int j = u + 16 * qi;
        float2 w1 = tw[j], w2 = tw[2*j], w3 = tw[3*j];
        x[qi]   = caddf(t3, t4);
        x[qi+2] = cmulf(csubf(t3, t4), w2);
        x[qi+4] = cmulf(make_float2(t1.x + t2.y, t1.y - t2.x), w1);
        x[qi+6] = cmulf(make_float2(t1.x - t2.y, t1.y + t2.x), w3);
    }
    {
        float2 w = tw[u << 2];
        #pragma unroll
        for (int i = 0; i < 8; i += 2) {
            float2 a = x[i], b = x[i+1];
            x[i]   = caddf(a, b);
            x[i+1] = cmulf(csubf(a, b), w);
        }
    }
    #pragma unroll
    for (int s = 3; s < 7; ++s) {
        int h = 64 >> s;
        bool lower = (u & h) == 0;
        float sgn = lower ? 1.0f : -1.0f;
        float2 wst = tw[(u & (h - 1)) << s];
        float2 we  = lower ? make_float2(1.0f, 0.0f) : wst;
        #pragma unroll
        for (int i = 0; i < 8; ++i) {
            float2 v = x[i];
            float2 o = shflx(v, h);
            float2 t = make_float2(fmaf(sgn, v.x, o.x), fmaf(sgn, v.y, o.y));
            x[i] = cmulf(t, we);
        }
    }
}

// Inverse DIT (unnormalized): bit-reversed in -> natural out.
__device__ __forceinline__ void fft128_inv(float2 x[8], int u, const float2* __restrict__ tw) {
    #pragma unroll
    for (int s = 6; s >= 3; --s) {
        int h = 64 >> s;
        bool lower = (u & h) == 0;
        float sgn = lower ? 1.0f : -1.0f;
        float2 wst = tw[(u & (h - 1)) << s];
        float2 we  = lower ? make_float2(1.0f, 0.0f) : make_float2(wst.x, -wst.y);
        #pragma unroll
        for (int i = 0; i < 8; ++i) {
            float2 t = cmulf(x[i], we);
            float2 o = shflx(t, h);
            x[i] = make_float2(fmaf(sgn, t.x, o.x), fmaf(sgn, t.y, o.y));
        }
    }
    {
        float2 w = tw[u << 2]; w.y = -w.y;
        #pragma unroll
        for (int i = 0; i < 8; i += 2) {
            float2 a = x[i], v = cmulf(x[i+1], w);
            x[i]   = caddf(a, v);
            x[i+1] = csubf(a, v);
        }
    }
    #pragma unroll
    for (int qi = 0; qi < 2; ++qi) {
        float2 a = x[qi], b = x[qi+2], c = x[qi+4], d = x[qi+6];
        int j = u + 16 * qi;
        float2 w1 = tw[j],   w2 = tw[2*j],   w3 = tw[3*j];
        w1.y = -w1.y; w2.y = -w2.y; w3.y = -w3.y;
        float2 s1 = cmulf(b, w2);
        float2 s2 = cmulf(c, w1);
        float2 s3 = cmulf(d, w3);
        float2 t3 = caddf(a, s1);
        float2 t4 = csubf(a, s1);
        float2 t1 = caddf(s2, s3);
        float2 t2 = make_float2(s3.y - s2.y, s2.x - s3.x);
        x[qi]   = caddf(t3, t1);
        x[qi+4] = csubf(t3, t1);
        x[qi+2] = caddf(t4, t2);
        x[qi+6] = csubf(t4, t2);
    }
}

// Deterministic block reduction; valid on tid==0. One __syncthreads inside.
template<int NWARPS>
__device__ __forceinline__ float block_sum(float v, float* red, int tid) {
    #pragma unroll
    for (int o = 16; o > 0; o >>= 1) v += __shfl_down_sync(0xffffffffu, v, o);
    if ((tid & 31) == 0) red[tid >> 5] = v;
    __syncthreads();
    float total = 0.0f;
    if (tid == 0) {
        #pragma unroll
        for (int w = 0; w < NWARPS; ++w) total += red[w];
    }
    return total;
}

// Pruned inverse-row pass: process only rows with |kr| <= B (bitrev addresses),
// zero-fill the rest. src/ps in bitrev order. All shuffles stay full-warp converged
// (trip counts are uniform per warp). Writes fp16 plane S.
__device__ __forceinline__ void inv_rows_pruned(
    __half2* S, const float2* __restrict__ src, const float* __restrict__ ps,
    const float2* __restrict__ tw, int B, int tid, int u, int hf, int w)
{
    int n = 2 * B + 1;
    int npair = (n + 1) >> 1;
    for (int t = w; t < npair; t += NTS / 32) {
        int idx = 2 * t + hf;
        if (idx >= n) idx = n - 1;                 // duplicate last row (benign)
        int kr = idx - B;
        int r = __brev((unsigned)(kr & 127)) >> 25;
        float2 x[8];
        #pragma unroll
        for (int i = 0; i < 8; ++i) {
            int p = r * NN + u + 16*i;
            float2 v = src[p];
            float  f = ps[p];
            x[i] = make_float2(v.x * f, v.y * f);
        }
        fft128_inv(x, u, tw);
        #pragma unroll
        for (int i = 0; i < 8; ++i) S[r * STRH + u + 16*i] = __float22half2_rn(x[i]);
    }
    // zero inactive rows: unsigned freqs [B+1, 127-B] are exactly the inactive set
    const __half2 hz = __float22half2_rn(make_float2(0.0f, 0.0f));
    int nz = (127 - 2 * B) * 128;
    for (int z = tid; z < nz; z += NTS) {
        int fu = B + 1 + (z >> 7);
        int a = __brev((unsigned)fu) >> 25;
        S[a * STRH + (z & 127)] = hz;
    }
}

// Full (unpruned) inverse-row pass with the conflict-free static row map.
__device__ __forceinline__ void inv_rows_full(
    __half2* S, const float2* __restrict__ src, const float* __restrict__ ps,
    const float2* __restrict__ tw, int u, int rw)
{
    #pragma unroll
    for (int iter = 0; iter < 4; ++iter) {
        int r = rw + 32 * iter;
        float2 x[8];
        #pragma unroll
        for (int i = 0; i < 8; ++i) {
            int p = r * NN + u + 16*i;
            float2 v = src[p];
            float  f = ps[p];
            x[i] = make_float2(v.x * f, v.y * f);
        }
        fft128_inv(x, u, tw);
        #pragma unroll
        for (int i = 0; i < 8; ++i) S[r * STRH + u + 16*i] = __float22half2_rn(x[i]);
    }
}

// ---------------- kernel 1: Morlet bank, pre-permuted to 2D-bitrev ----------------
__global__ void k_psi() {
    int idx = blockIdx.x * blockDim.x + threadIdx.x;
    if (idx >= NJ * NL * PLANE) return;
    int p   = idx >> 14;
    int pos = idx & (PLANE - 1);
    int R = pos >> 7, C = pos & 127;
    int r = __brev((unsigned)R) >> 25;
    int c = __brev((unsigned)C) >> 25;
    int j = p >> 2, l = p & 3;
    float fr = (float)(r < 64 ? r : r - 128) * (6.283185307179586f / 128.0f);
    float fc = (float)(c < 64 ? c : c - 128) * (6.283185307179586f / 128.0f);
    float k0    = 2.356194490192345f / (float)(1 << j);
    float sigma = 0.8f * (float)(1 << j);
    float s2    = sigma * sigma;
    float theta = 0.7853981633974483f * (float)l;
    float k0x = k0 * cosf(theta), k0y = k0 * sinf(theta);
    float beta = expf(-0.5f * s2 * k0 * k0);
    float dx = fr - k0x, dy = fc - k0y;
    float g1 = expf(-0.5f * s2 * (dx*dx + dy*dy));
    float g0 = expf(-0.5f * s2 * (fr*fr + fc*fc));
    g_psi[idx] = g1 - beta * g0;
}

// ---------------- kernel 2: fft2(image) + s0 (fp32 everywhere, 64 blocks) ----------------
__global__ void __launch_bounds__(NTI, 1) k_img(const float* __restrict__ img) {
    extern __shared__ unsigned char smraw[];
    float2* S   = (float2*)smraw;
    float2* tw  = S + NN * STRIDE;
    float*  red = (float*)(tw + 128);
    int b = blockIdx.x, tid = threadIdx.x;
    int u = tid & 15, g = tid >> 4;
    init_tw(tw, tid);
    __syncthreads();
    const float* ip = img + (size_t)b * PLANE;
    float lsum = 0.0f;
    #pragma unroll
    for (int iter = 0; iter < 2; ++iter) {
        int r = g + 64 * iter;
        float2 x[8];
        #pragma unroll
        for (int i = 0; i < 8; ++i) {
            float v = ip[r * NN + u + 16*i];
            lsum += v;
            x[i] = make_float2(v, 0.0f);
        }
        fft128_fwd(x, u, tw);
        #pragma unroll
        for (int i = 0; i < 8; ++i) S[r * STRIDE + u + 16*i] = x[i];
    }
    float tot = block_sum<NTI/32>(lsum, red, tid);
    if (tid == 0) g_s0[b] = tot * (1.0f / 16384.0f);
    #pragma unroll
    for (int iter = 0; iter < 2; ++iter) {
        int c = g + 64 * iter;
        float2 x[8];
        #pragma unroll
        for (int i = 0; i < 8; ++i) x[i] = S[(u + 16*i) * STRIDE + c];
        fft128_fwd(x, u, tw);
        #pragma unroll
        for (int i = 0; i < 8; ++i) S[(u + 16*i) * STRIDE + c] = x[i];
    }
    __syncthreads();
    float2* op = g_ihat + (size_t)b * PLANE;
    for (int i = tid; i < PLANE; i += NTI)
        op[i] = S[(i >> 7) * STRIDE + (i & 127)];
}

// ---------------- kernel 3: order 1 (fp16 shared, 2 CTAs/SM, pruned rows) ----------------
__global__ void __launch_bounds__(NTS, 2) k_o1() {
    extern __shared__ unsigned char smraw[];
    __half2* S  = (__half2*)smraw;
    float2*  tw = (float2*)(smraw + SH_PLANE_BYTES);
    float*   red= (float*)(tw + 128);
    int tid = threadIdx.x;
    int u = tid & 15, hf = (tid >> 4) & 1, w = tid >> 5;
    int rw = (w + (w & 8)) + hf * 8;      // warp rows map, disjoint banks
    int cw = 2 * w + hf;                  // warp cols map, even/odd banks
    int b  = blockIdx.x >> 4;
    int j1 = (blockIdx.x >> 2) & 3;
    int l1 = blockIdx.x & 3;
    init_tw(tw, tid);
    __syncthreads();
    const float2* ih = g_ihat + (size_t)b * PLANE;
    const float*  ps = g_psi + (size_t)(j1 * NL + l1) * PLANE;
    int B = BMAX[j1];
    if (B >= 64) inv_rows_full(S, ih, ps, tw, u, rw);
    else         inv_rows_pruned(S, ih, ps, tw, B, tid, u, hf, w);
    __syncthreads();
    float lsum = 0.0f;
    #pragma unroll
    for (int iter = 0; iter < 4; ++iter) {          // inverse cols -> |.| -> forward cols
        int c = cw + 32 * iter;
        float2 x[8];
        #pragma unroll
        for (int i = 0; i < 8; ++i) x[i] = __half22float2(S[(u + 16*i) * STRH + c]);
        fft128_inv(x, u, tw);
        #pragma unroll
        for (int i = 0; i < 8; ++i) {
            float m = fast_mag(x[i]) * (1.0f / 16384.0f);
            lsum += m;
            x[i] = make_float2(m, 0.0f);
        }
        fft128_fwd(x, u, tw);
        #pragma unroll
        for (int i = 0; i < 8; ++i) S[(u + 16*i) * STRH + c] = __float22half2_rn(x[i]);
    }
    float tot = block_sum<NTS/32>(lsum, red, tid);  // sync inside orders S stores
    if (tid == 0) g_s1p[blockIdx.x] = tot;
    float2* op = g_u1hat + (size_t)blockIdx.x * PLANE;
    #pragma unroll
    for (int iter = 0; iter < 4; ++iter) {          // forward rows, write out from regs
        int r = rw + 32 * iter;
        float2 x[8];
        #pragma unroll
        for (int i = 0; i < 8; ++i) x[i] = __half22float2(S[r * STRH + u + 16*i]);
        fft128_fwd(x, u, tw);
        #pragma unroll
        for (int i = 0; i < 8; ++i) op[r * NN + u + 16*i] = x[i];
    }
}

// ---------------- kernel 4: order 2 (fp16 shared, 2 CTAs/SM, pruned rows) ----------------
__global__ void __launch_bounds__(NTS, 2) k_o2() {
    extern __shared__ unsigned char smraw[];
    __half2* S  = (__half2*)smraw;
    float2*  tw = (float2*)(smraw + SH_PLANE_BYTES);
    float*   red= (float*)(tw + 128);
    int tid = threadIdx.x;
    int u = tid & 15, hf = (tid >> 4) & 1, w = tid >> 5;
    int rw = (w + (w & 8)) + hf * 8;
    int cw = 2 * w + hf;
    int b    = blockIdx.x / 96;
    int rem  = blockIdx.x - b * 96;
    int pair = rem >> 4;
    int l1   = (rem >> 2) & 3;
    int l2   = rem & 3;
    int j1 = PJ1[pair], j2 = PJ2[pair];
    init_tw(tw, tid);
    __syncthreads();
    const float2* uh = g_u1hat + (size_t)(((b * NJ + j1) * NL) + l1) * PLANE;
    const float*  ps = g_psi + (size_t)(j2 * NL + l2) * PLANE;
    int B = BMAX[j2];
    if (B >= 64) inv_rows_full(S, uh, ps, tw, u, rw);
    else         inv_rows_pruned(S, uh, ps, tw, B, tid, u, hf, w);
    __syncthreads();
    float lsum = 0.0f;
    #pragma unroll
    for (int iter = 0; iter < 4; ++iter) {          // inverse cols, |.| from regs
        int c = cw + 32 * iter;
        float2 x[8];
        #pragma unroll
        for (int i = 0; i < 8; ++i) x[i] = __half22float2(S[(u + 16*i) * STRH + c]);
        fft128_inv(x, u, tw);
        #pragma unroll
        for (int i = 0; i < 8; ++i)
            lsum += fast_mag(x[i]);
    }
    float tot = block_sum<NTS/32>(lsum, red, tid);
    if (tid == 0) g_s2p[blockIdx.x] = tot;
}

// ---------------- kernel 5: combine + MLP ----------------
__global__ void k_head(const float* __restrict__ fc1w, const float* __restrict__ fc1b,
                       const float* __restrict__ fc2w, const float* __restrict__ fc2b,
                       float* __restrict__ out) {
    int b = blockIdx.x;
    if (threadIdx.x != 0) return;
    float coeff[11];
    coeff[0] = g_s0[b];
    #pragma unroll
    for (int j = 0; j < 4; ++j) {
        float s = 0.0f;
        #pragma unroll
        for (int l = 0; l < 4; ++l) s += g_s1p[(b * 4 + j) * 4 + l];
        coeff[1 + j] = s * (1.0f / (4.0f * 16384.0f));
    }
    #pragma unroll
    for (int p = 0; p < 6; ++p) {
        float s = 0.0f;
        #pragma unroll
        for (int k = 0; k < 16; ++k) s += g_s2p[(b * 6 + p) * 16 + k];
        coeff[5 + p] = s * (1.0f / 16384.0f) * (1.0f / (16.0f * 16384.0f));
    }
    float h[4];
    #pragma unroll
    for (int k = 0; k < 4; ++k) {
        float a = fc1b[k];
        #pragma unroll
        for (int i = 0; i < 11; ++i) a += coeff[i] * fc1w[k * 11 + i];
        h[k] = fmaxf(a, 0.0f);
    }
    #pragma unroll
    for (int o = 0; o < 10; ++o) {
        float a = fc2b[o];
        #pragma unroll
        for (int k = 0; k < 4; ++k) a += h[k] * fc2w[o * 4 + k];
        out[b * 10 + o] = 1.0f / (1.0f + expf(-a));
    }
}

// ---------------- launch ----------------
extern "C" void kernel_launch(void* const* d_in, const int* in_sizes, int n_in,
                              void* d_out, int out_size) {
    (void)in_sizes; (void)n_in; (void)out_size;
    const float* img  = (const float*)d_in[0];
    const float* fc1w = (const float*)d_in[1];
    const float* fc1b = (const float*)d_in[2];
    const float* fc2w = (const float*)d_in[3];
    const float* fc2b = (const float*)d_in[4];
    float* out = (float*)d_out;

    const size_t SMEM_IMG = (size_t)(NN * STRIDE + 128) * sizeof(float2) + (NTI / 32) * sizeof(float);
    const size_t SMEM_O   = SH_PLANE_BYTES + 128 * sizeof(float2) + (NTS / 32) * sizeof(float);
    cudaFuncSetAttribute(k_img, cudaFuncAttributeMaxDynamicSharedMemorySize, (int)SMEM_IMG);
    cudaFuncSetAttribute(k_o1,  cudaFuncAttributeMaxDynamicSharedMemorySize, (int)SMEM_O);
    cudaFuncSetAttribute(k_o2,  cudaFuncAttributeMaxDynamicSharedMemorySize, (int)SMEM_O);

    k_psi<<<(NJ * NL * PLANE + 255) / 256, 256>>>();
    k_img<<<BATCH, NTI, SMEM_IMG>>>(img);
    k_o1 <<<BATCH * NJ * NL, NTS, SMEM_O>>>();
    k_o2 <<<BATCH * NPAIR * NL * NL, NTS, SMEM_O>>>();
    k_head<<<BATCH, 32>>>(fc1w, fc1b, fc2w, fc2b, out);
}

// round 11
// speedup vs baseline: 1.9866x; 1.0259x over previous
#include <cuda_runtime.h>
#include <cuda_fp16.h>
#include <math.h>

#define NN     128
#define PLANE  16384
#define STRIDE 129            // fp32 plane stride (k_img)
#define STRH   130            // half2 plane stride (k_o1/k_o2)
#define BATCH  64
#define NJ     4
#define NL     4
#define NPAIR  6
#define NTI    1024           // k_img threads
#define NTS    512            // k_o1/k_o2 threads (2 CTAs/SM)

#define SH_PLANE_BYTES (NN * STRH * sizeof(__half2))   // 66560

// ---------------- device scratch ----------------
static __device__ float2  g_ihat [BATCH * PLANE];                 // bitrev order, fp32
static __device__ __half2 g_u1hat[BATCH * 3 * NL * PLANE];        // bitrev, fp16, j1<3 only
static __device__ float   g_psi  [NJ * NL * PLANE];               // bitrev order
static __device__ float   g_s0   [BATCH];
static __device__ float   g_s1p  [BATCH * NJ * NL];
static __device__ float   g_s2p  [BATCH * NPAIR * NL * NL];

__device__ __constant__ int PJ1[NPAIR] = {0,0,0,1,1,2};
__device__ __constant__ int PJ2[NPAIR] = {1,2,3,2,3,3};
// row-frequency support bound per scale j: |kr| <= B (k0 + 5*sigma_f, bins). 64 = full.
__device__ __constant__ int BMAX[NJ] = {64, 64, 44, 22};

// ---------------- helpers ----------------
__device__ __forceinline__ float2 cmulf(float2 a, float2 b) {
    return make_float2(a.x*b.x - a.y*b.y, a.x*b.y + a.y*b.x);
}
__device__ __forceinline__ float2 caddf(float2 a, float2 b){ return make_float2(a.x+b.x, a.y+b.y); }
__device__ __forceinline__ float2 csubf(float2 a, float2 b){ return make_float2(a.x-b.x, a.y-b.y); }

__device__ __forceinline__ void init_tw(float2* tw, int tid) {
    if (tid < 128) {
        float s, c;
        __sincosf(-6.283185307179586f * (float)tid * (1.0f/128.0f), &s, &c);
        tw[tid] = make_float2(c, s);   // W_128^k
    }
}

__device__ __forceinline__ float2 shflx(float2 v, int h) {
    float2 o;
    o.x = __shfl_xor_sync(0xffffffffu, v.x, h);
    o.y = __shfl_xor_sync(0xffffffffu, v.y, h);
    return o;
}

__device__ __forceinline__ float fast_mag(float2 z) {
    float m2 = fmaf(z.x, z.x, z.y * z.y);
    float r;
    asm("sqrt.approx.f32 %0, %1;" : "=f"(r) : "f"(m2));
    return r;
}

// source loaders (fp32 or fp16 planes)
__device__ __forceinline__ float2 ld2(const float2* p, int i)  { return p[i]; }
__device__ __forceinline__ float2 ld2(const __half2* p, int i) { return __half22float2(p[i]); }

// ---------------- 128-pt FFT: 16 lanes x 8 regs, position p = u + 16*i ----------------
// Forward DIF: natural in -> bit-reversed out.
__device__ __forceinline__ void fft128_fwd(float2 x[8], int u, const float2* __restrict__ tw) {
    #pragma unroll
    for (int qi = 0; qi < 2; ++qi) {
        float2 a = x[qi], b = x[qi+2], c = x[qi+4], d = x[qi+6];
        float2 t3 = caddf(a, c), t1 = csubf(a, c);
        float2 t4 = caddf(b, d), t2 = csubf(b, d);
        int j = u + 16 * qi;
        float2 w1 = tw[j], w2 = tw[2*j], w3 = tw[3*j];
        x[qi]   = caddf(t3, t4);
        x[qi+2] = cmulf(csubf(t3, t4), w2);
        x[qi+4] = cmulf(make_float2(t1.x + t2.y, t1.y - t2.x), w1);
        x[qi+6] = cmulf(make_float2(t1.x - t2.y, t1.y + t2.x), w3);
    }
    {
        float2 w = tw[u << 2];
        #pragma unroll
        for (int i = 0; i < 8; i += 2) {
            float2 a = x[i], b = x[i+1];
            x[i]   = caddf(a, b);
            x[i+1] = cmulf(csubf(a, b), w);
        }
    }
    #pragma unroll
    for (int s = 3; s < 6; ++s) {
        int h = 64 >> s;
        bool lower = (u & h) == 0;
        float sgn = lower ? 1.0f : -1.0f;
        float2 wst = tw[(u & (h - 1)) << s];
        float2 we  = lower ? make_float2(1.0f, 0.0f) : wst;
        #pragma unroll
        for (int i = 0; i < 8; ++i) {
            float2 v = x[i];
            float2 o = shflx(v, h);
            float2 t = make_float2(fmaf(sgn, v.x, o.x), fmaf(sgn, v.y, o.y));
            x[i] = cmulf(t, we);
        }
    }
    {   // s=6, h=1: twiddle == (1,0) for ALL lanes -> no cmul
        bool lower = (u & 1) == 0;
        float sgn = lower ? 1.0f : -1.0f;
        #pragma unroll
        for (int i = 0; i < 8; ++i) {
            float2 v = x[i];
            float2 o = shflx(v, 1);
            x[i] = make_float2(fmaf(sgn, v.x, o.x), fmaf(sgn, v.y, o.y));
        }
    }
}

// Inverse DIT (unnormalized): bit-reversed in -> natural out.
__device__ __forceinline__ void fft128_inv(float2 x[8], int u, const float2* __restrict__ tw) {
    {   // s=6 (h=1): twiddle == (1,0) for ALL lanes -> no cmul
        bool lower = (u & 1) == 0;
        float sgn = lower ? 1.0f : -1.0f;
        #pragma unroll
        for (int i = 0; i < 8; ++i) {
            float2 t = x[i];
            float2 o = shflx(t, 1);
            x[i] = make_float2(fmaf(sgn, t.x, o.x), fmaf(sgn, t.y, o.y));
        }
    }
    #pragma unroll
    for (int s = 5; s >= 3; --s) {
        int h = 64 >> s;
        bool lower = (u & h) == 0;
        float sgn = lower ? 1.0f : -1.0f;
        float2 wst = tw[(u & (h - 1)) << s];
        float2 we  = lower ? make_float2(1.0f, 0.0f) : make_float2(wst.x, -wst.y);
        #pragma unroll
        for (int i = 0; i < 8; ++i) {
            float2 t = cmulf(x[i], we);
            float2 o = shflx(t, h);
            x[i] = make_float2(fmaf(sgn, t.x, o.x), fmaf(sgn, t.y, o.y));
        }
    }
    {
        float2 w = tw[u << 2]; w.y = -w.y;
        #pragma unroll
        for (int i = 0; i < 8; i += 2) {
            float2 a = x[i], v = cmulf(x[i+1], w);
            x[i]   = caddf(a, v);
            x[i+1] = csubf(a, v);
        }
    }
    #pragma unroll
    for (int qi = 0; qi < 2; ++qi) {
        float2 a = x[qi], b = x[qi+2], c = x[qi+4], d = x[qi+6];
        int j = u + 16 * qi;
        float2 w1 = tw[j],   w2 = tw[2*j],   w3 = tw[3*j];
        w1.y = -w1.y; w2.y = -w2.y; w3.y = -w3.y;
        float2 s1 = cmulf(b, w2);
        float2 s2 = cmulf(c, w1);
        float2 s3 = cmulf(d, w3);
        float2 t3 = caddf(a, s1);
        float2 t4 = csubf(a, s1);
        float2 t1 = caddf(s2, s3);
        float2 t2 = make_float2(s3.y - s2.y, s2.x - s3.x);
        x[qi]   = caddf(t3, t1);
        x[qi+4] = csubf(t3, t1);
        x[qi+2] = caddf(t4, t2);
        x[qi+6] = csubf(t4, t2);
    }
}

// Deterministic block reduction; valid on tid==0. One __syncthreads inside.
template<int NWARPS>
__device__ __forceinline__ float block_sum(float v, float* red, int tid) {
    #pragma unroll
    for (int o = 16; o > 0; o >>= 1) v += __shfl_down_sync(0xffffffffu, v, o);
    if ((tid & 31) == 0) red[tid >> 5] = v;
    __syncthreads();
    float total = 0.0f;
    if (tid == 0) {
        #pragma unroll
        for (int w = 0; w < NWARPS; ++w) total += red[w];
    }
    return total;
}

// Pruned inverse-row pass (|kr| <= B active), zero-fill the rest. Uniform warp trips.
template<typename SRC>
__device__ __forceinline__ void inv_rows_pruned(
    __half2* S, const SRC* __restrict__ src, const float* __restrict__ ps,
    const float2* __restrict__ tw, int B, int tid, int u, int hf, int w)
{
    int n = 2 * B + 1;
    int npair = (n + 1) >> 1;
    for (int t = w; t < npair; t += NTS / 32) {
        int idx = 2 * t + hf;
        if (idx >= n) idx = n - 1;                 // duplicate last row (benign)
        int kr = idx - B;
        int r = __brev((unsigned)(kr & 127)) >> 25;
        float2 x[8];
        #pragma unroll
        for (int i = 0; i < 8; ++i) {
            int p = r * NN + u + 16*i;
            float2 v = ld2(src, p);
            float  f = ps[p];
            x[i] = make_float2(v.x * f, v.y * f);
        }
        fft128_inv(x, u, tw);
        #pragma unroll
        for (int i = 0; i < 8; ++i) S[r * STRH + u + 16*i] = __float22half2_rn(x[i]);
    }
    const __half2 hz = __float22half2_rn(make_float2(0.0f, 0.0f));
    int nz = (127 - 2 * B) * 128;
    for (int z = tid; z < nz; z += NTS) {
        int fu = B + 1 + (z >> 7);
        int a = __brev((unsigned)fu) >> 25;
        S[a * STRH + (z & 127)] = hz;
    }
}

// Full (unpruned) inverse-row pass with the conflict-free static row map.
template<typename SRC>
__device__ __forceinline__ void inv_rows_full(
    __half2* S, const SRC* __restrict__ src, const float* __restrict__ ps,
    const float2* __restrict__ tw, int u, int rw)
{
    #pragma unroll
    for (int iter = 0; iter < 4; ++iter) {
        int r = rw + 32 * iter;
        float2 x[8];
        #pragma unroll
        for (int i = 0; i < 8; ++i) {
            int p = r * NN + u + 16*i;
            float2 v = ld2(src, p);
            float  f = ps[p];
            x[i] = make_float2(v.x * f, v.y * f);
        }
        fft128_inv(x, u, tw);
        #pragma unroll
        for (int i = 0; i < 8; ++i) S[r * STRH + u + 16*i] = __float22half2_rn(x[i]);
    }
}

// ---------------- kernel 1: Morlet bank, pre-permuted to 2D-bitrev ----------------
__global__ void k_psi() {
    int idx = blockIdx.x * blockDim.x + threadIdx.x;
    if (idx >= NJ * NL * PLANE) return;
    int p   = idx >> 14;
    int pos = idx & (PLANE - 1);
    int R = pos >> 7, C = pos & 127;
    int r = __brev((unsigned)R) >> 25;
    int c = __brev((unsigned)C) >> 25;
    int j = p >> 2, l = p & 3;
    float fr = (float)(r < 64 ? r : r - 128) * (6.283185307179586f / 128.0f);
    float fc = (float)(c < 64 ? c : c - 128) * (6.283185307179586f / 128.0f);
    float k0    = 2.356194490192345f / (float)(1 << j);
    float sigma = 0.8f * (float)(1 << j);
    float s2    = sigma * sigma;
    float theta = 0.7853981633974483f * (float)l;
    float k0x = k0 * cosf(theta), k0y = k0 * sinf(theta);
    float beta = expf(-0.5f * s2 * k0 * k0);
    float dx = fr - k0x, dy = fc - k0y;
    float g1 = expf(-0.5f * s2 * (dx*dx + dy*dy));
    float g0 = expf(-0.5f * s2 * (fr*fr + fc*fc));
    g_psi[idx] = g1 - beta * g0;
}

// ---------------- kernel 2: fft2(image) + s0 (fp32, 64 blocks) ----------------
__global__ void __launch_bounds__(NTI, 1) k_img(const float* __restrict__ img) {
    extern __shared__ unsigned char smraw[];
    float2* S   = (float2*)smraw;
    float2* tw  = S + NN * STRIDE;
    float*  red = (float*)(tw + 128);
    int b = blockIdx.x, tid = threadIdx.x;
    int u = tid & 15, g = tid >> 4;
    init_tw(tw, tid);
    __syncthreads();
    const float* ip = img + (size_t)b * PLANE;
    float lsum = 0.0f;
    #pragma unroll
    for (int iter = 0; iter < 2; ++iter) {
        int r = g + 64 * iter;
        float2 x[8];
        #pragma unroll
        for (int i = 0; i < 8; ++i) {
            float v = ip[r * NN + u + 16*i];
            lsum += v;
            x[i] = make_float2(v, 0.0f);
        }
        fft128_fwd(x, u, tw);
        #pragma unroll
        for (int i = 0; i < 8; ++i) S[r * STRIDE + u + 16*i] = x[i];
    }
    float tot = block_sum<NTI/32>(lsum, red, tid);
    if (tid == 0) g_s0[b] = tot * (1.0f / 16384.0f);
    #pragma unroll
    for (int iter = 0; iter < 2; ++iter) {
        int c = g + 64 * iter;
        float2 x[8];
        #pragma unroll
        for (int i = 0; i < 8; ++i) x[i] = S[(u + 16*i) * STRIDE + c];
        fft128_fwd(x, u, tw);
        #pragma unroll
        for (int i = 0; i < 8; ++i) S[(u + 16*i) * STRIDE + c] = x[i];
    }
    __syncthreads();
    float2* op = g_ihat + (size_t)b * PLANE;
    for (int i = tid; i < PLANE; i += NTI)
        op[i] = S[(i >> 7) * STRIDE + (i & 127)];
}

// ---------------- kernel 3: order 1 (fp16 shared, pruned rows, j1=3 early-out) ----------------
__global__ void __launch_bounds__(NTS, 2) k_o1() {
    extern __shared__ unsigned char smraw[];
    __half2* S  = (__half2*)smraw;
    float2*  tw = (float2*)(smraw + SH_PLANE_BYTES);
    float*   red= (float*)(tw + 128);
    int tid = threadIdx.x;
    int u = tid & 15, hf = (tid >> 4) & 1, w = tid >> 5;
    int rw = (w + (w & 8)) + hf * 8;      // warp rows map, disjoint banks
    int cw = 2 * w + hf;                  // warp cols map, even/odd banks
    int b  = blockIdx.x >> 4;
    int j1 = (blockIdx.x >> 2) & 3;
    int l1 = blockIdx.x & 3;
    init_tw(tw, tid);
    __syncthreads();
    const float2* ih = g_ihat + (size_t)b * PLANE;
    const float*  ps = g_psi + (size_t)(j1 * NL + l1) * PLANE;
    int B = BMAX[j1];
    bool produce = (j1 < 3);              // j1=3 u1hat planes are never consumed
    if (B >= 64) inv_rows_full(S, ih, ps, tw, u, rw);
    else         inv_rows_pruned(S, ih, ps, tw, B, tid, u, hf, w);
    __syncthreads();
    float lsum = 0.0f;
    #pragma unroll
    for (int iter = 0; iter < 4; ++iter) {          // inverse cols -> |.| (-> forward cols)
        int c = cw + 32 * iter;
        float2 x[8];
        #pragma unroll
        for (int i = 0; i < 8; ++i) x[i] = __half22float2(S[(u + 16*i) * STRH + c]);
        fft128_inv(x, u, tw);
        #pragma unroll
        for (int i = 0; i < 8; ++i) {
            float m = fast_mag(x[i]) * (1.0f / 16384.0f);
            lsum += m;
            x[i] = make_float2(m, 0.0f);
        }
        if (produce) {
            fft128_fwd(x, u, tw);
            #pragma unroll
            for (int i = 0; i < 8; ++i) S[(u + 16*i) * STRH + c] = __float22half2_rn(x[i]);
        }
    }
    float tot = block_sum<NTS/32>(lsum, red, tid);  // sync inside orders S stores
    if (tid == 0) g_s1p[blockIdx.x] = tot;
    if (produce) {
        __half2* op = g_u1hat + (size_t)((b * 3 + j1) * NL + l1) * PLANE;
        #pragma unroll
        for (int iter = 0; iter < 4; ++iter) {      // forward rows, write out fp16
            int r = rw + 32 * iter;
            float2 x[8];
            #pragma unroll
            for (int i = 0; i < 8; ++i) x[i] = __half22float2(S[r * STRH + u + 16*i]);
            fft128_fwd(x, u, tw);
            #pragma unroll
            for (int i = 0; i < 8; ++i) op[r * NN + u + 16*i] = __float22half2_rn(x[i]);
        }
    }
}

// ---------------- kernel 4: order 2 (fp16 shared + fp16 u1hat, pruned rows) ----------------
__global__ void __launch_bounds__(NTS, 2) k_o2() {
    extern __shared__ unsigned char smraw[];
    __half2* S  = (__half2*)smraw;
    float2*  tw = (float2*)(smraw + SH_PLANE_BYTES);
    float*   red= (float*)(tw + 128);
    int tid = threadIdx.x;
    int u = tid & 15, hf = (tid >> 4) & 1, w = tid >> 5;
    int rw = (w + (w & 8)) + hf * 8;
    int cw = 2 * w + hf;
    int b    = blockIdx.x / 96;
    int rem  = blockIdx.x - b * 96;
    int pair = rem >> 4;
    int l1   = (rem >> 2) & 3;
    int l2   = rem & 3;
    int j1 = PJ1[pair], j2 = PJ2[pair];
    init_tw(tw, tid);
    __syncthreads();
    const __half2* uh = g_u1hat + (size_t)((b * 3 + j1) * NL + l1) * PLANE;
    const float*   ps = g_psi + (size_t)(j2 * NL + l2) * PLANE;
    int B = BMAX[j2];
    if (B >= 64) inv_rows_full(S, uh, ps, tw, u, rw);
    else         inv_rows_pruned(S, uh, ps, tw, B, tid, u, hf, w);
    __syncthreads();
    float lsum = 0.0f;
    #pragma unroll
    for (int iter = 0; iter < 4; ++iter) {          // inverse cols, |.| from regs
        int c = cw + 32 * iter;
        float2 x[8];
        #pragma unroll
        for (int i = 0; i < 8; ++i) x[i] = __half22float2(S[(u + 16*i) * STRH + c]);
        fft128_inv(x, u, tw);
        #pragma unroll
        for (int i = 0; i < 8; ++i)
            lsum += fast_mag(x[i]);
    }
    float tot = block_sum<NTS/32>(lsum, red, tid);
    if (tid == 0) g_s2p[blockIdx.x] = tot;
}

// ---------------- kernel 5: combine + MLP ----------------
__global__ void k_head(const float* __restrict__ fc1w, const float* __restrict__ fc1b,
                       const float* __restrict__ fc2w, const float* __restrict__ fc2b,
                       float* __restrict__ out) {
    int b = blockIdx.x;
    if (threadIdx.x != 0) return;
    float coeff[11];
    coeff[0] = g_s0[b];
    #pragma unroll
    for (int j = 0; j < 4; ++j) {
        float s = 0.0f;
        #pragma unroll
        for (int l = 0; l < 4; ++l) s += g_s1p[(b * 4 + j) * 4 + l];
        coeff[1 + j] = s * (1.0f / (4.0f * 16384.0f));
    }
    #pragma unroll
    for (int p = 0; p < 6; ++p) {
        float s = 0.0f;
        #pragma unroll
        for (int k = 0; k < 16; ++k) s += g_s2p[(b * 6 + p) * 16 + k];
        coeff[5 + p] = s * (1.0f / 16384.0f) * (1.0f / (16.0f * 16384.0f));
    }
    float h[4];
    #pragma unroll
    for (int k = 0; k < 4; ++k) {
        float a = fc1b[k];
        #pragma unroll
        for (int i = 0; i < 11; ++i) a += coeff[i] * fc1w[k * 11 + i];
        h[k] = fmaxf(a, 0.0f);
    }
    #pragma unroll
    for (int o = 0; o < 10; ++o) {
        float a = fc2b[o];
        #pragma unroll
        for (int k = 0; k < 4; ++k) a += h[k] * fc2w[o * 4 + k];
        out[b * 10 + o] = 1.0f / (1.0f + expf(-a));
    }
}

// ---------------- launch ----------------
extern "C" void kernel_launch(void* const* d_in, const int* in_sizes, int n_in,
                              void* d_out, int out_size) {
    (void)in_sizes; (void)n_in; (void)out_size;
    const float* img  = (const float*)d_in[0];
    const float* fc1w = (const float*)d_in[1];
    const float* fc1b = (const float*)d_in[2];
    const float* fc2w = (const float*)d_in[3];
    const float* fc2b = (const float*)d_in[4];
    float* out = (float*)d_out;

    const size_t SMEM_IMG = (size_t)(NN * STRIDE + 128) * sizeof(float2) + (NTI / 32) * sizeof(float);
    const size_t SMEM_O   = SH_PLANE_BYTES + 128 * sizeof(float2) + (NTS / 32) * sizeof(float);
    cudaFuncSetAttribute(k_img, cudaFuncAttributeMaxDynamicSharedMemorySize, (int)SMEM_IMG);
    cudaFuncSetAttribute(k_o1,  cudaFuncAttributeMaxDynamicSharedMemorySize, (int)SMEM_O);
    cudaFuncSetAttribute(k_o2,  cudaFuncAttributeMaxDynamicSharedMemorySize, (int)SMEM_O);

    k_psi<<<(NJ * NL * PLANE + 255) / 256, 256>>>();
    k_img<<<BATCH, NTI, SMEM_IMG>>>(img);
    k_o1 <<<BATCH * NJ * NL, NTS, SMEM_O>>>();
    k_o2 <<<BATCH * NPAIR * NL * NL, NTS, SMEM_O>>>();
    k_head<<<BATCH, 32>>>(fc1w, fc1b, fc2w, fc2b, out);
}

// round 12
// speedup vs baseline: 2.3519x; 1.1839x over previous
#include <cuda_runtime.h>
#include <cuda_fp16.h>
#include <math.h>

#define NN     128
#define PLANE  16384
#define STRIDE 129            // fp32 plane stride (k_img)
#define STRH   130            // half2 plane stride (k_o1/k_o2)
#define BATCH  64
#define NJ     4
#define NL     4
#define NPAIR  6
#define NTI    1024           // k_img threads
#define NTS    512            // k_o1/k_o2 threads (2 CTAs/SM)

#define SH_PLANE_BYTES (NN * STRH * sizeof(__half2))   // 66560
#define TW_OFF   SH_PLANE_BYTES
#define HC_OFF   (TW_OFF + 128 * sizeof(float2))
#define HS_OFF   (HC_OFF + 128 * sizeof(__half2))
#define RED_OFF  (HS_OFF + 128 * sizeof(__half2))
#define SMEM_O_TOT (RED_OFF + (NTS / 32) * sizeof(float))

// ---------------- device scratch ----------------
static __device__ float2  g_ihat [BATCH * PLANE];                 // bitrev order, fp32
static __device__ __half2 g_u1hat[BATCH * 3 * NL * PLANE];        // bitrev, fp16, j1<3 only
static __device__ float   g_psi  [NJ * NL * PLANE];               // bitrev order
static __device__ float   g_s0   [BATCH];
static __device__ float   g_s1p  [BATCH * NJ * NL];
static __device__ float   g_s2p  [BATCH * NPAIR * NL * NL];

__device__ __constant__ int PJ1[NPAIR] = {0,0,0,1,1,2};
__device__ __constant__ int PJ2[NPAIR] = {1,2,3,2,3,3};
// row-frequency support bound per scale j: |kr| <= B (k0 + 5*sigma_f). 64 = full.
__device__ __constant__ int BMAX[NJ] = {64, 64, 44, 22};

// ---------------- fp32 helpers ----------------
__device__ __forceinline__ float2 cmulf(float2 a, float2 b) {
    return make_float2(a.x*b.x - a.y*b.y, a.x*b.y + a.y*b.x);
}
__device__ __forceinline__ float2 caddf(float2 a, float2 b){ return make_float2(a.x+b.x, a.y+b.y); }
__device__ __forceinline__ float2 csubf(float2 a, float2 b){ return make_float2(a.x-b.x, a.y-b.y); }

__device__ __forceinline__ float2 shflx(float2 v, int h) {
    float2 o;
    o.x = __shfl_xor_sync(0xffffffffu, v.x, h);
    o.y = __shfl_xor_sync(0xffffffffu, v.y, h);
    return o;
}

__device__ __forceinline__ float fast_mag(float2 z) {
    float m2 = fmaf(z.x, z.x, z.y * z.y);
    float r;
    asm("sqrt.approx.f32 %0, %1;" : "=f"(r) : "f"(m2));
    return r;
}

__device__ __forceinline__ float2 ld2(const float2* p, int i)  { return p[i]; }
__device__ __forceinline__ float2 ld2(const __half2* p, int i) { return __half22float2(p[i]); }

// ---------------- half2 dual-complex helpers ----------------
struct HC { __half2 re, im; };

__device__ __forceinline__ __half2 shxh(__half2 v, int h) {
    unsigned q = __shfl_xor_sync(0xffffffffu, *reinterpret_cast<unsigned*>(&v), h);
    return *reinterpret_cast<__half2*>(&q);
}
__device__ __forceinline__ HC hcmul(HC a, __half2 wre, __half2 wim) {
    HC r;
    r.re = __hsub2(__hmul2(a.re, wre), __hmul2(a.im, wim));
    r.im = __hfma2(a.re, wim, __hmul2(a.im, wre));
    return r;
}

// ---------------- 128-pt FFT (fp32): 16 lanes x 8 regs, p = u + 16*i ----------------
__device__ __forceinline__ void fft128_fwd(float2 x[8], int u, const float2* __restrict__ tw) {
    #pragma unroll
    for (int qi = 0; qi < 2; ++qi) {
        float2 a = x[qi], b = x[qi+2], c = x[qi+4], d = x[qi+6];
        float2 t3 = caddf(a, c), t1 = csubf(a, c);
        float2 t4 = caddf(b, d), t2 = csubf(b, d);
        int j = u + 16 * qi;
        float2 w1 = tw[j], w2 = tw[2*j], w3 = tw[3*j];
        x[qi]   = caddf(t3, t4);
        x[qi+2] = cmulf(csubf(t3, t4), w2);
        x[qi+4] = cmulf(make_float2(t1.x + t2.y, t1.y - t2.x), w1);
        x[qi+6] = cmulf(make_float2(t1.x - t2.y, t1.y + t2.x), w3);
    }
    {
        float2 w = tw[u << 2];
        #pragma unroll
        for (int i = 0; i < 8; i += 2) {
            float2 a = x[i], b = x[i+1];
            x[i]   = caddf(a, b);
            x[i+1] = cmulf(csubf(a, b), w);
        }
    }
    #pragma unroll
    for (int s = 3; s < 6; ++s) {
        int h = 64 >> s;
        bool lower = (u & h) == 0;
        float sgn = lower ? 1.0f : -1.0f;
        float2 wst = tw[(u & (h - 1)) << s];
        float2 we  = lower ? make_float2(1.0f, 0.0f) : wst;
        #pragma unroll
        for (int i = 0; i < 8; ++i) {
            float2 v = x[i];
            float2 o = shflx(v, h);
            float2 t = make_float2(fmaf(sgn, v.x, o.x), fmaf(sgn, v.y, o.y));
            x[i] = cmulf(t, we);
        }
    }
    {   // s=6, h=1: twiddle == 1
        bool lower = (u & 1) == 0;
        float sgn = lower ? 1.0f : -1.0f;
        #pragma unroll
        for (int i = 0; i < 8; ++i) {
            float2 v = x[i];
            float2 o = shflx(v, 1);
            x[i] = make_float2(fmaf(sgn, v.x, o.x), fmaf(sgn, v.y, o.y));
        }
    }
}

__device__ __forceinline__ void fft128_inv(float2 x[8], int u, const float2* __restrict__ tw) {
    {   // s=6, h=1
        bool lower = (u & 1) == 0;
        float sgn = lower ? 1.0f : -1.0f;
        #pragma unroll
        for (int i = 0; i < 8; ++i) {
            float2 t = x[i];
            float2 o = shflx(t, 1);
            x[i] = make_float2(fmaf(sgn, t.x, o.x), fmaf(sgn, t.y, o.y));
        }
    }
    #pragma unroll
    for (int s = 5; s >= 3; --s) {
        int h = 64 >> s;
        bool lower = (u & h) == 0;
        float sgn = lower ? 1.0f : -1.0f;
        float2 wst = tw[(u & (h - 1)) << s];
        float2 we  = lower ? make_float2(1.0f, 0.0f) : make_float2(wst.x, -wst.y);
        #pragma unroll
        for (int i = 0; i < 8; ++i) {
            float2 t = cmulf(x[i], we);
            float2 o = shflx(t, h);
            x[i] = make_float2(fmaf(sgn, t.x, o.x), fmaf(sgn, t.y, o.y));
        }
    }
    {
        float2 w = tw[u << 2]; w.y = -w.y;
        #pragma unroll
        for (int i = 0; i < 8; i += 2) {
            float2 a = x[i], v = cmulf(x[i+1], w);
            x[i]   = caddf(a, v);
            x[i+1] = csubf(a, v);
        }
    }
    #pragma unroll
    for (int qi = 0; qi < 2; ++qi) {
        float2 a = x[qi], b = x[qi+2], c = x[qi+4], d = x[qi+6];
        int j = u + 16 * qi;
        float2 w1 = tw[j],   w2 = tw[2*j],   w3 = tw[3*j];
        w1.y = -w1.y; w2.y = -w2.y; w3.y = -w3.y;
        float2 s1 = cmulf(b, w2);
        float2 s2 = cmulf(c, w1);
        float2 s3 = cmulf(d, w3);
        float2 t3 = caddf(a, s1);
        float2 t4 = csubf(a, s1);
        float2 t1 = caddf(s2, s3);
        float2 t2 = make_float2(s3.y - s2.y, s2.x - s3.x);
        x[qi]   = caddf(t3, t1);
        x[qi+4] = csubf(t3, t1);
        x[qi+2] = caddf(t4, t2);
        x[qi+6] = csubf(t4, t2);
    }
}

// ---------------- dual-column inverse FFT in half2 SIMD (2 columns at once) ----------------
__device__ __forceinline__ void fft128_inv_h2(HC x[8], int u,
        const __half2* __restrict__ hc, const __half2* __restrict__ hs) {
    const __half2 ONE  = __float2half2_rn(1.0f);
    const __half2 ZERO = __float2half2_rn(0.0f);
    {   // s=6, h=1: w == 1
        __half2 sg = __float2half2_rn(((u & 1) == 0) ? 1.0f : -1.0f);
        #pragma unroll
        for (int i = 0; i < 8; ++i) {
            __half2 orr = shxh(x[i].re, 1), oii = shxh(x[i].im, 1);
            x[i].re = __hfma2(sg, x[i].re, orr);
            x[i].im = __hfma2(sg, x[i].im, oii);
        }
    }
    #pragma unroll
    for (int s = 5; s >= 3; --s) {
        int h = 64 >> s;
        bool lower = (u & h) == 0;
        __half2 sg = __float2half2_rn(lower ? 1.0f : -1.0f);
        int k = (u & (h - 1)) << s;
        __half2 wre = lower ? ONE  : hc[k];
        __half2 wim = lower ? ZERO : __hneg2(hs[k]);
        #pragma unroll
        for (int i = 0; i < 8; ++i) {
            HC t = hcmul(x[i], wre, wim);
            __half2 orr = shxh(t.re, h), oii = shxh(t.im, h);
            x[i].re = __hfma2(sg, t.re, orr);
            x[i].im = __hfma2(sg, t.im, oii);
        }
    }
    {   // m=16 stage: w = conj(tw[u<<2])
        __half2 wre = hc[u << 2], wim = __hneg2(hs[u << 2]);
        #pragma unroll
        for (int i = 0; i < 8; i += 2) {
            HC v = hcmul(x[i+1], wre, wim);
            HC a = x[i];
            x[i].re   = __hadd2(a.re, v.re);  x[i].im   = __hadd2(a.im, v.im);
            x[i+1].re = __hsub2(a.re, v.re);  x[i+1].im = __hsub2(a.im, v.im);
        }
    }
    #pragma unroll
    for (int qi = 0; qi < 2; ++qi) {
        int j = u + 16 * qi;
        __half2 w1re = hc[j],   w1im = __hneg2(hs[j]);
        __half2 w2re = hc[2*j], w2im = __hneg2(hs[2*j]);
        __half2 w3re = hc[3*j], w3im = __hneg2(hs[3*j]);
        HC a = x[qi], b = x[qi+2], c = x[qi+4], d = x[qi+6];
        HC s1 = hcmul(b, w2re, w2im);
        HC s2 = hcmul(c, w1re, w1im);
        HC s3 = hcmul(d, w3re, w3im);
        HC t3, t4, t1, t2;
        t3.re = __hadd2(a.re, s1.re);  t3.im = __hadd2(a.im, s1.im);
        t4.re = __hsub2(a.re, s1.re);  t4.im = __hsub2(a.im, s1.im);
        t1.re = __hadd2(s2.re, s3.re); t1.im = __hadd2(s2.im, s3.im);
        t2.re = __hsub2(s3.im, s2.im); t2.im = __hsub2(s2.re, s3.re);
        x[qi].re   = __hadd2(t3.re, t1.re); x[qi].im   = __hadd2(t3.im, t1.im);
        x[qi+4].re = __hsub2(t3.re, t1.re); x[qi+4].im = __hsub2(t3.im, t1.im);
        x[qi+2].re = __hadd2(t4.re, t2.re); x[qi+2].im = __hadd2(t4.im, t2.im);
        x[qi+6].re = __hsub2(t4.re, t2.re); x[qi+6].im = __hsub2(t4.im, t2.im);
    }
}

// Deterministic block reduction; valid on tid==0. One __syncthreads inside.
template<int NWARPS>
__device__ __forceinline__ float block_sum(float v, float* red, int tid) {
    #pragma unroll
    for (int o = 16; o > 0; o >>= 1) v += __shfl_down_sync(0xffffffffu, v, o);
    if ((tid & 31) == 0) red[tid >> 5] = v;
    __syncthreads();
    float total = 0.0f;
    if (tid == 0) {
        #pragma unroll
        for (int w = 0; w < NWARPS; ++w) total += red[w];
    }
    return total;
}

// Pruned inverse-row pass (|kr| <= B active), zero-fill the rest. scale folds norm.
template<typename SRC>
__device__ __forceinline__ void inv_rows_pruned(
    __half2* S, const SRC* __restrict__ src, const float* __restrict__ ps, float scale,
    const float2* __restrict__ tw, int B, int tid, int u, int hf, int w)
{
    int n = 2 * B + 1;
    int npair = (n + 1) >> 1;
    for (int t = w; t < npair; t += NTS / 32) {
        int idx = 2 * t + hf;
        if (idx >= n) idx = n - 1;                 // duplicate last row (benign)
        int kr = idx - B;
        int r = __brev((unsigned)(kr & 127)) >> 25;
        float2 x[8];
        #pragma unroll
        for (int i = 0; i < 8; ++i) {
            int p = r * NN + u + 16*i;
            float2 v = ld2(src, p);
            float  f = ps[p] * scale;
            x[i] = make_float2(v.x * f, v.y * f);
        }
        fft128_inv(x, u, tw);
        #pragma unroll
        for (int i = 0; i < 8; ++i) S[r * STRH + u + 16*i] = __float22half2_rn(x[i]);
    }
    const __half2 hz = __float22half2_rn(make_float2(0.0f, 0.0f));
    int nz = (127 - 2 * B) * 128;
    for (int z = tid; z < nz; z += NTS) {
        int fu = B + 1 + (z >> 7);
        int a = __brev((unsigned)fu) >> 25;
        S[a * STRH + (z & 127)] = hz;
    }
}

template<typename SRC>
__device__ __forceinline__ void inv_rows_full(
    __half2* S, const SRC* __restrict__ src, const float* __restrict__ ps, float scale,
    const float2* __restrict__ tw, int u, int rw)
{
    #pragma unroll
    for (int iter = 0; iter < 4; ++iter) {
        int r = rw + 32 * iter;
        float2 x[8];
        #pragma unroll
        for (int i = 0; i < 8; ++i) {
            int p = r * NN + u + 16*i;
            float2 v = ld2(src, p);
            float  f = ps[p] * scale;
            x[i] = make_float2(v.x * f, v.y * f);
        }
        fft128_inv(x, u, tw);
        #pragma unroll
        for (int i = 0; i < 8; ++i) S[r * STRH + u + 16*i] = __float22half2_rn(x[i]);
    }
}

// ---------------- kernel 1: Morlet bank, pre-permuted to 2D-bitrev ----------------
__global__ void k_psi() {
    int idx = blockIdx.x * blockDim.x + threadIdx.x;
    if (idx >= NJ * NL * PLANE) return;
    int p   = idx >> 14;
    int pos = idx & (PLANE - 1);
    int R = pos >> 7, C = pos & 127;
    int r = __brev((unsigned)R) >> 25;
    int c = __brev((unsigned)C) >> 25;
    int j = p >> 2, l = p & 3;
    float fr = (float)(r < 64 ? r : r - 128) * (6.283185307179586f / 128.0f);
    float fc = (float)(c < 64 ? c : c - 128) * (6.283185307179586f / 128.0f);
    float k0    = 2.356194490192345f / (float)(1 << j);
    float sigma = 0.8f * (float)(1 << j);
    float s2    = sigma * sigma;
    float theta = 0.7853981633974483f * (float)l;
    float k0x = k0 * cosf(theta), k0y = k0 * sinf(theta);
    float beta = expf(-0.5f * s2 * k0 * k0);
    float dx = fr - k0x, dy = fc - k0y;
    float g1 = expf(-0.5f * s2 * (dx*dx + dy*dy));
    float g0 = expf(-0.5f * s2 * (fr*fr + fc*fc));
    g_psi[idx] = g1 - beta * g0;
}

// ---------------- kernel 2: fft2(image) + s0 (fp32, 64 blocks) ----------------
__global__ void __launch_bounds__(NTI, 1) k_img(const float* __restrict__ img) {
    extern __shared__ unsigned char smraw[];
    float2* S   = (float2*)smraw;
    float2* tw  = S + NN * STRIDE;
    float*  red = (float*)(tw + 128);
    int b = blockIdx.x, tid = threadIdx.x;
    int u = tid & 15, g = tid >> 4;
    if (tid < 128) {
        float s, c;
        __sincosf(-6.283185307179586f * (float)tid * (1.0f/128.0f), &s, &c);
        tw[tid] = make_float2(c, s);
    }
    __syncthreads();
    const float* ip = img + (size_t)b * PLANE;
    float lsum = 0.0f;
    #pragma unroll
    for (int iter = 0; iter < 2; ++iter) {
        int r = g + 64 * iter;
        float2 x[8];
        #pragma unroll
        for (int i = 0; i < 8; ++i) {
            float v = ip[r * NN + u + 16*i];
            lsum += v;
            x[i] = make_float2(v, 0.0f);
        }
        fft128_fwd(x, u, tw);
        #pragma unroll
        for (int i = 0; i < 8; ++i) S[r * STRIDE + u + 16*i] = x[i];
    }
    float tot = block_sum<NTI/32>(lsum, red, tid);
    if (tid == 0) g_s0[b] = tot * (1.0f / 16384.0f);
    #pragma unroll
    for (int iter = 0; iter < 2; ++iter) {
        int c = g + 64 * iter;
        float2 x[8];
        #pragma unroll
        for (int i = 0; i < 8; ++i) x[i] = S[(u + 16*i) * STRIDE + c];
        fft128_fwd(x, u, tw);
        #pragma unroll
        for (int i = 0; i < 8; ++i) S[(u + 16*i) * STRIDE + c] = x[i];
    }
    __syncthreads();
    float2* op = g_ihat + (size_t)b * PLANE;
    for (int i = tid; i < PLANE; i += NTI)
        op[i] = S[(i >> 7) * STRIDE + (i & 127)];
}

// ---------------- kernel 3: order 1 ----------------
__global__ void __launch_bounds__(NTS, 2) k_o1() {
    extern __shared__ unsigned char smraw[];
    __half2* S  = (__half2*)smraw;
    float2*  tw = (float2*)(smraw + TW_OFF);
    float*   red= (float*)(smraw + RED_OFF);
    int tid = threadIdx.x;
    int u = tid & 15, hf = (tid >> 4) & 1, w = tid >> 5;
    int rw = (w + (w & 8)) + hf * 8;
    int cw = 2 * w + hf;
    int b  = blockIdx.x >> 4;
    int j1 = (blockIdx.x >> 2) & 3;
    int l1 = blockIdx.x & 3;
    if (tid < 128) {
        float s, c;
        __sincosf(-6.283185307179586f * (float)tid * (1.0f/128.0f), &s, &c);
        tw[tid] = make_float2(c, s);
    }
    __syncthreads();
    const float2* ih = g_ihat + (size_t)b * PLANE;
    const float*  ps = g_psi + (size_t)(j1 * NL + l1) * PLANE;
    int B = BMAX[j1];
    bool produce = (j1 < 3);
    if (B >= 64) inv_rows_full(S, ih, ps, 1.0f, tw, u, rw);
    else         inv_rows_pruned(S, ih, ps, 1.0f, tw, B, tid, u, hf, w);
    __syncthreads();
    float lsum = 0.0f;
    #pragma unroll
    for (int iter = 0; iter < 4; ++iter) {          // inverse cols -> |.| (-> forward cols)
        int c = cw + 32 * iter;
        float2 x[8];
        #pragma unroll
        for (int i = 0; i < 8; ++i) x[i] = __half22float2(S[(u + 16*i) * STRH + c]);
        fft128_inv(x, u, tw);
        #pragma unroll
        for (int i = 0; i < 8; ++i) {
            float m = fast_mag(x[i]) * (1.0f / 16384.0f);
            lsum += m;
            x[i] = make_float2(m, 0.0f);
        }
        if (produce) {
            fft128_fwd(x, u, tw);
            #pragma unroll
            for (int i = 0; i < 8; ++i) S[(u + 16*i) * STRH + c] = __float22half2_rn(x[i]);
        }
    }
    float tot = block_sum<NTS/32>(lsum, red, tid);
    if (tid == 0) g_s1p[blockIdx.x] = tot;
    if (produce) {
        __half2* op = g_u1hat + (size_t)((b * 3 + j1) * NL + l1) * PLANE;
        int Bw = BMAX[j1 + 1];                      // max consumer bound (B decreasing in j)
        if (Bw >= 64) {
            #pragma unroll
            for (int iter = 0; iter < 4; ++iter) {
                int r = rw + 32 * iter;
                float2 x[8];
                #pragma unroll
                for (int i = 0; i < 8; ++i) x[i] = __half22float2(S[r * STRH + u + 16*i]);
                fft128_fwd(x, u, tw);
                #pragma unroll
                for (int i = 0; i < 8; ++i) op[r * NN + u + 16*i] = __float22half2_rn(x[i]);
            }
        } else {
            // only rows |kr| <= Bw are ever read by k_o2 (consumer pruning)
            int n = 2 * Bw + 1, npair = (n + 1) >> 1;
            for (int t = w; t < npair; t += NTS / 32) {
                int idx = 2 * t + hf;
                if (idx >= n) idx = n - 1;
                int kr = idx - Bw;
                int r = __brev((unsigned)(kr & 127)) >> 25;
                float2 x[8];
                #pragma unroll
                for (int i = 0; i < 8; ++i) x[i] = __half22float2(S[r * STRH + u + 16*i]);
                fft128_fwd(x, u, tw);
                #pragma unroll
                for (int i = 0; i < 8; ++i) op[r * NN + u + 16*i] = __float22half2_rn(x[i]);
            }
        }
    }
}

// ---------------- kernel 4: order 2 (dual-column half2 col pass) ----------------
__global__ void __launch_bounds__(NTS, 2) k_o2() {
    extern __shared__ unsigned char smraw[];
    __half2* S  = (__half2*)smraw;
    float2*  tw = (float2*)(smraw + TW_OFF);
    __half2* hc = (__half2*)(smraw + HC_OFF);
    __half2* hs = (__half2*)(smraw + HS_OFF);
    float*   red= (float*)(smraw + RED_OFF);
    int tid = threadIdx.x;
    int u = tid & 15, hf = (tid >> 4) & 1, w = tid >> 5;
    int rw = (w + (w & 8)) + hf * 8;
    int b    = blockIdx.x / 96;
    int rem  = blockIdx.x - b * 96;
    int pair = rem >> 4;
    int l1   = (rem >> 2) & 3;
    int l2   = rem & 3;
    int j1 = PJ1[pair], j2 = PJ2[pair];
    if (tid < 128) {
        float s, c;
        __sincosf(-6.283185307179586f * (float)tid * (1.0f/128.0f), &s, &c);
        tw[tid] = make_float2(c, s);
        hc[tid] = __float2half2_rn(c);
        hs[tid] = __float2half2_rn(s);
    }
    __syncthreads();
    const __half2* uh = g_u1hat + (size_t)((b * 3 + j1) * NL + l1) * PLANE;
    const float*   ps = g_psi + (size_t)(j2 * NL + l2) * PLANE;
    int B = BMAX[j2];
    const float SC = 1.0f / 16384.0f;               // fold ifft norm -> fp16-safe range
    if (B >= 64) inv_rows_full(S, uh, ps, SC, tw, u, rw);
    else         inv_rows_pruned(S, uh, ps, SC, tw, B, tid, u, hf, w);
    __syncthreads();
    float lsum = 0.0f;
    // dual-column inverse: warp w covers cols {4w..4w+3}; hf0 -> (4w,4w+2), hf1 -> (4w+1,4w+3)
    #pragma unroll
    for (int iter = 0; iter < 2; ++iter) {
        int c0 = 4 * w + hf + 64 * iter;
        int c1 = c0 + 2;
        HC x[8];
        #pragma unroll
        for (int i = 0; i < 8; ++i) {
            __half2 a = S[(u + 16*i) * STRH + c0];
            __half2 bb = S[(u + 16*i) * STRH + c1];
            x[i].re = __lows2half2(a, bb);
            x[i].im = __highs2half2(a, bb);
        }
        fft128_inv_h2(x, u, hc, hs);
        #pragma unroll
        for (int i = 0; i < 8; ++i) {
            float2 re = __half22float2(x[i].re);
            float2 im = __half22float2(x[i].im);
            lsum += fast_mag(make_float2(re.x, im.x));
            lsum += fast_mag(make_float2(re.y, im.y));
        }
    }
    float tot = block_sum<NTS/32>(lsum, red, tid);
    if (tid == 0) g_s2p[blockIdx.x] = tot;
}

// ---------------- kernel 5: combine + MLP ----------------
__global__ void k_head(const float* __restrict__ fc1w, const float* __restrict__ fc1b,
                       const float* __restrict__ fc2w, const float* __restrict__ fc2b,
                       float* __restrict__ out) {
    int b = blockIdx.x;
    if (threadIdx.x != 0) return;
    float coeff[11];
    coeff[0] = g_s0[b];
    #pragma unroll
    for (int j = 0; j < 4; ++j) {
        float s = 0.0f;
        #pragma unroll
        for (int l = 0; l < 4; ++l) s += g_s1p[(b * 4 + j) * 4 + l];
        coeff[1 + j] = s * (1.0f / (4.0f * 16384.0f));
    }
    #pragma unroll
    for (int p = 0; p < 6; ++p) {
        float s = 0.0f;
        #pragma unroll
        for (int k = 0; k < 16; ++k) s += g_s2p[(b * 6 + p) * 16 + k];
        coeff[5 + p] = s * (1.0f / (16.0f * 16384.0f));   // ifft norm folded into k_o2
    }
    float h[4];
    #pragma unroll
    for (int k = 0; k < 4; ++k) {
        float a = fc1b[k];
        #pragma unroll
        for (int i = 0; i < 11; ++i) a += coeff[i] * fc1w[k * 11 + i];
        h[k] = fmaxf(a, 0.0f);
    }
    #pragma unroll
    for (int o = 0; o < 10; ++o) {
        float a = fc2b[o];
        #pragma unroll
        for (int k = 0; k < 4; ++k) a += h[k] * fc2w[o * 4 + k];
        out[b * 10 + o] = 1.0f / (1.0f + expf(-a));
    }
}

// ---------------- launch ----------------
extern "C" void kernel_launch(void* const* d_in, const int* in_sizes, int n_in,
                              void* d_out, int out_size) {
    (void)in_sizes; (void)n_in; (void)out_size;
    const float* img  = (const float*)d_in[0];
    const float* fc1w = (const float*)d_in[1];
    const float* fc1b = (const float*)d_in[2];
    const float* fc2w = (const float*)d_in[3];
    const float* fc2b = (const float*)d_in[4];
    float* out = (float*)d_out;

    const size_t SMEM_IMG = (size_t)(NN * STRIDE + 128) * sizeof(float2) + (NTI / 32) * sizeof(float);
    const size_t SMEM_O   = SMEM_O_TOT;
    cudaFuncSetAttribute(k_img, cudaFuncAttributeMaxDynamicSharedMemorySize, (int)SMEM_IMG);
    cudaFuncSetAttribute(k_o1,  cudaFuncAttributeMaxDynamicSharedMemorySize, (int)SMEM_O);
    cudaFuncSetAttribute(k_o2,  cudaFuncAttributeMaxDynamicSharedMemorySize, (int)SMEM_O);

    k_psi<<<(NJ * NL * PLANE + 255) / 256, 256>>>();
    k_img<<<BATCH, NTI, SMEM_IMG>>>(img);
    k_o1 <<<BATCH * NJ * NL, NTS, SMEM_O>>>();
    k_o2 <<<BATCH * NPAIR * NL * NL, NTS, SMEM_O>>>();
    k_head<<<BATCH, 32>>>(fc1w, fc1b, fc2w, fc2b, out);
}

// round 14
// speedup vs baseline: 2.3890x; 1.0158x over previous
#include <cuda_runtime.h>
#include <cuda_fp16.h>
#include <math.h>

#define NN     128
#define PLANE  16384
#define STRIDE 129            // fp32 plane stride (k_img)
#define STRH   130            // half2 plane stride (k_o1/k_o2)
#define BATCH  64
#define NJ     4
#define NL     4
#define NPAIR  6
#define NTI    1024           // k_img threads
#define NTS    512            // k_o1/k_o2 threads (2 CTAs/SM)

#define SH_PLANE_BYTES (NN * STRH * sizeof(__half2))   // 66560
#define TW_OFF   SH_PLANE_BYTES
#define HC_OFF   (TW_OFF + 128 * sizeof(float2))
#define HS_OFF   (HC_OFF + 128 * sizeof(__half2))
#define RED_OFF  (HS_OFF + 128 * sizeof(__half2))
#define SMEM_O_TOT (RED_OFF + (NTS / 32) * sizeof(float))

// ---------------- device scratch ----------------
static __device__ float2  g_ihat [BATCH * PLANE];                 // bitrev order, fp32
static __device__ __half2 g_u1hat[BATCH * 3 * NL * PLANE];        // bitrev, fp16, j1<3 only
static __device__ float   g_psi  [NJ * NL * PLANE];               // bitrev order
static __device__ float   g_s0   [BATCH];
static __device__ float   g_s1p  [BATCH * NJ * NL];
static __device__ float   g_s2p  [BATCH * NPAIR * NL * NL];

__device__ __constant__ int PJ1[NPAIR] = {0,0,0,1,1,2};
__device__ __constant__ int PJ2[NPAIR] = {1,2,3,2,3,3};
// row-frequency support bound per scale j: |kr| <= B (k0 + 5*sigma_f). 64 = full.
__device__ __constant__ int BMAX[NJ] = {64, 64, 44, 22};

// ---------------- fp32 helpers ----------------
__device__ __forceinline__ float2 cmulf(float2 a, float2 b) {
    return make_float2(a.x*b.x - a.y*b.y, a.x*b.y + a.y*b.x);
}
__device__ __forceinline__ float2 caddf(float2 a, float2 b){ return make_float2(a.x+b.x, a.y+b.y); }
__device__ __forceinline__ float2 csubf(float2 a, float2 b){ return make_float2(a.x-b.x, a.y-b.y); }

__device__ __forceinline__ float2 shflx(float2 v, int h) {
    float2 o;
    o.x = __shfl_xor_sync(0xffffffffu, v.x, h);
    o.y = __shfl_xor_sync(0xffffffffu, v.y, h);
    return o;
}

__device__ __forceinline__ float fast_mag(float2 z) {
    float m2 = fmaf(z.x, z.x, z.y * z.y);
    float r;
    asm("sqrt.approx.f32 %0, %1;" : "=f"(r) : "f"(m2));
    return r;
}

__device__ __forceinline__ float2 ld2(const float2* p, int i)  { return p[i]; }
__device__ __forceinline__ float2 ld2(const __half2* p, int i) { return __half22float2(p[i]); }

// ---------------- half2 dual-complex helpers ----------------
struct HC { __half2 re, im; };

__device__ __forceinline__ __half2 shxh(__half2 v, int h) {
    unsigned q = __shfl_xor_sync(0xffffffffu, *reinterpret_cast<unsigned*>(&v), h);
    return *reinterpret_cast<__half2*>(&q);
}
__device__ __forceinline__ HC hcmul(HC a, __half2 wre, __half2 wim) {
    HC r;
    r.re = __hsub2(__hmul2(a.re, wre), __hmul2(a.im, wim));
    r.im = __hfma2(a.re, wim, __hmul2(a.im, wre));
    return r;
}

// ---------------- 128-pt FFT (fp32): 16 lanes x 8 regs, p = u + 16*i ----------------
__device__ __forceinline__ void fft128_fwd(float2 x[8], int u, const float2* __restrict__ tw) {
    #pragma unroll
    for (int qi = 0; qi < 2; ++qi) {
        float2 a = x[qi], b = x[qi+2], c = x[qi+4], d = x[qi+6];
        float2 t3 = caddf(a, c), t1 = csubf(a, c);
        float2 t4 = caddf(b, d), t2 = csubf(b, d);
        int j = u + 16 * qi;
        float2 w1 = tw[j], w2 = tw[2*j], w3 = tw[3*j];
        x[qi]   = caddf(t3, t4);
        x[qi+2] = cmulf(csubf(t3, t4), w2);
        x[qi+4] = cmulf(make_float2(t1.x + t2.y, t1.y - t2.x), w1);
        x[qi+6] = cmulf(make_float2(t1.x - t2.y, t1.y + t2.x), w3);
    }
    {
        float2 w = tw[u << 2];
        #pragma unroll
        for (int i = 0; i < 8; i += 2) {
            float2 a = x[i], b = x[i+1];
            x[i]   = caddf(a, b);
            x[i+1] = cmulf(csubf(a, b), w);
        }
    }
    #pragma unroll
    for (int s = 3; s < 6; ++s) {
        int h = 64 >> s;
        bool lower = (u & h) == 0;
        float sgn = lower ? 1.0f : -1.0f;
        float2 wst = tw[(u & (h - 1)) << s];
        float2 we  = lower ? make_float2(1.0f, 0.0f) : wst;
        #pragma unroll
        for (int i = 0; i < 8; ++i) {
            float2 v = x[i];
            float2 o = shflx(v, h);
            float2 t = make_float2(fmaf(sgn, v.x, o.x), fmaf(sgn, v.y, o.y));
            x[i] = cmulf(t, we);
        }
    }
    {   // s=6, h=1: twiddle == 1
        bool lower = (u & 1) == 0;
        float sgn = lower ? 1.0f : -1.0f;
        #pragma unroll
        for (int i = 0; i < 8; ++i) {
            float2 v = x[i];
            float2 o = shflx(v, 1);
            x[i] = make_float2(fmaf(sgn, v.x, o.x), fmaf(sgn, v.y, o.y));
        }
    }
}

__device__ __forceinline__ void fft128_inv(float2 x[8], int u, const float2* __restrict__ tw) {
    {   // s=6, h=1
        bool lower = (u & 1) == 0;
        float sgn = lower ? 1.0f : -1.0f;
        #pragma unroll
        for (int i = 0; i < 8; ++i) {
            float2 t = x[i];
            float2 o = shflx(t, 1);
            x[i] = make_float2(fmaf(sgn, t.x, o.x), fmaf(sgn, t.y, o.y));
        }
    }
    #pragma unroll
    for (int s = 5; s >= 3; --s) {
        int h = 64 >> s;
        bool lower = (u & h) == 0;
        float sgn = lower ? 1.0f : -1.0f;
        float2 wst = tw[(u & (h - 1)) << s];
        float2 we  = lower ? make_float2(1.0f, 0.0f) : make_float2(wst.x, -wst.y);
        #pragma unroll
        for (int i = 0; i < 8; ++i) {
            float2 t = cmulf(x[i], we);
            float2 o = shflx(t, h);
            x[i] = make_float2(fmaf(sgn, t.x, o.x), fmaf(sgn, t.y, o.y));
        }
    }
    {
        float2 w = tw[u << 2]; w.y = -w.y;
        #pragma unroll
        for (int i = 0; i < 8; i += 2) {
            float2 a = x[i], v = cmulf(x[i+1], w);
            x[i]   = caddf(a, v);
            x[i+1] = csubf(a, v);
        }
    }
    #pragma unroll
    for (int qi = 0; qi < 2; ++qi) {
        float2 a = x[qi], b = x[qi+2], c = x[qi+4], d = x[qi+6];
        int j = u + 16 * qi;
        float2 w1 = tw[j],   w2 = tw[2*j],   w3 = tw[3*j];
        w1.y = -w1.y; w2.y = -w2.y; w3.y = -w3.y;
        float2 s1 = cmulf(b, w2);
        float2 s2 = cmulf(c, w1);
        float2 s3 = cmulf(d, w3);
        float2 t3 = caddf(a, s1);
        float2 t4 = csubf(a, s1);
        float2 t1 = caddf(s2, s3);
        float2 t2 = make_float2(s3.y - s2.y, s2.x - s3.x);
        x[qi]   = caddf(t3, t1);
        x[qi+4] = csubf(t3, t1);
        x[qi+2] = caddf(t4, t2);
        x[qi+6] = csubf(t4, t2);
    }
}

// ---------------- dual inverse FFT in half2 SIMD (2 independent signals) ----------------
__device__ __forceinline__ void fft128_inv_h2(HC x[8], int u,
        const __half2* __restrict__ hc, const __half2* __restrict__ hs) {
    const __half2 ONE  = __float2half2_rn(1.0f);
    const __half2 ZERO = __float2half2_rn(0.0f);
    {   // s=6, h=1: w == 1
        __half2 sg = __float2half2_rn(((u & 1) == 0) ? 1.0f : -1.0f);
        #pragma unroll
        for (int i = 0; i < 8; ++i) {
            __half2 orr = shxh(x[i].re, 1), oii = shxh(x[i].im, 1);
            x[i].re = __hfma2(sg, x[i].re, orr);
            x[i].im = __hfma2(sg, x[i].im, oii);
        }
    }
    #pragma unroll
    for (int s = 5; s >= 3; --s) {
        int h = 64 >> s;
        bool lower = (u & h) == 0;
        __half2 sg = __float2half2_rn(lower ? 1.0f : -1.0f);
        int k = (u & (h - 1)) << s;
        __half2 wre = lower ? ONE  : hc[k];
        __half2 wim = lower ? ZERO : __hneg2(hs[k]);
        #pragma unroll
        for (int i = 0; i < 8; ++i) {
            HC t = hcmul(x[i], wre, wim);
            __half2 orr = shxh(t.re, h), oii = shxh(t.im, h);
            x[i].re = __hfma2(sg, t.re, orr);
            x[i].im = __hfma2(sg, t.im, oii);
        }
    }
    {   // m=16 stage: w = conj(tw[u<<2])
        __half2 wre = hc[u << 2], wim = __hneg2(hs[u << 2]);
        #pragma unroll
        for (int i = 0; i < 8; i += 2) {
            HC v = hcmul(x[i+1], wre, wim);
            HC a = x[i];
            x[i].re   = __hadd2(a.re, v.re);  x[i].im   = __hadd2(a.im, v.im);
            x[i+1].re = __hsub2(a.re, v.re);  x[i+1].im = __hsub2(a.im, v.im);
        }
    }
    #pragma unroll
    for (int qi = 0; qi < 2; ++qi) {
        int j = u + 16 * qi;
        __half2 w1re = hc[j],   w1im = __hneg2(hs[j]);
        __half2 w2re = hc[2*j], w2im = __hneg2(hs[2*j]);
        __half2 w3re = hc[3*j], w3im = __hneg2(hs[3*j]);
        HC a = x[qi], b = x[qi+2], c = x[qi+4], d = x[qi+6];
        HC s1 = hcmul(b, w2re, w2im);
        HC s2 = hcmul(c, w1re, w1im);
        HC s3 = hcmul(d, w3re, w3im);
        HC t3, t4, t1, t2;
        t3.re = __hadd2(a.re, s1.re);  t3.im = __hadd2(a.im, s1.im);
        t4.re = __hsub2(a.re, s1.re);  t4.im = __hsub2(a.im, s1.im);
        t1.re = __hadd2(s2.re, s3.re); t1.im = __hadd2(s2.im, s3.im);
        t2.re = __hsub2(s3.im, s2.im); t2.im = __hsub2(s2.re, s3.re);
        x[qi].re   = __hadd2(t3.re, t1.re); x[qi].im   = __hadd2(t3.im, t1.im);
        x[qi+4].re = __hsub2(t3.re, t1.re); x[qi+4].im = __hsub2(t3.im, t1.im);
        x[qi+2].re = __hadd2(t4.re, t2.re); x[qi+2].im = __hadd2(t4.im, t2.im);
        x[qi+6].re = __hsub2(t4.re, t2.re); x[qi+6].im = __hsub2(t4.im, t2.im);
    }
}

// Deterministic block reduction; valid on tid==0. One __syncthreads inside.
template<int NWARPS>
__device__ __forceinline__ float block_sum(float v, float* red, int tid) {
    #pragma unroll
    for (int o = 16; o > 0; o >>= 1) v += __shfl_down_sync(0xffffffffu, v, o);
    if ((tid & 31) == 0) red[tid >> 5] = v;
    __syncthreads();
    float total = 0.0f;
    if (tid == 0) {
        #pragma unroll
        for (int w = 0; w < NWARPS; ++w) total += red[w];
    }
    return total;
}

// Pruned inverse-row pass (fp32 FFT), zero-fill the rest. Used by k_o1.
template<typename SRC>
__device__ __forceinline__ void inv_rows_pruned(
    __half2* S, const SRC* __restrict__ src, const float* __restrict__ ps, float scale,
    const float2* __restrict__ tw, int B, int tid, int u, int hf, int w)
{
    int n = 2 * B + 1;
    int npair = (n + 1) >> 1;
    for (int t = w; t < npair; t += NTS / 32) {
        int idx = 2 * t + hf;
        if (idx >= n) idx = n - 1;
        int kr = idx - B;
        int r = __brev((unsigned)(kr & 127)) >> 25;
        float2 x[8];
        #pragma unroll
        for (int i = 0; i < 8; ++i) {
            int p = r * NN + u + 16*i;
            float2 v = ld2(src, p);
            float  f = ps[p] * scale;
            x[i] = make_float2(v.x * f, v.y * f);
        }
        fft128_inv(x, u, tw);
        #pragma unroll
        for (int i = 0; i < 8; ++i) S[r * STRH + u + 16*i] = __float22half2_rn(x[i]);
    }
    const __half2 hz = __float22half2_rn(make_float2(0.0f, 0.0f));
    int nz = (127 - 2 * B) * 128;
    for (int z = tid; z < nz; z += NTS) {
        int fu = B + 1 + (z >> 7);
        int a = __brev((unsigned)fu) >> 25;
        S[a * STRH + (z & 127)] = hz;
    }
}

template<typename SRC>
__device__ __forceinline__ void inv_rows_full(
    __half2* S, const SRC* __restrict__ src, const float* __restrict__ ps, float scale,
    const float2* __restrict__ tw, int u, int rw)
{
    #pragma unroll
    for (int iter = 0; iter < 4; ++iter) {
        int r = rw + 32 * iter;
        float2 x[8];
        #pragma unroll
        for (int i = 0; i < 8; ++i) {
            int p = r * NN + u + 16*i;
            float2 v = ld2(src, p);
            float  f = ps[p] * scale;
            x[i] = make_float2(v.x * f, v.y * f);
        }
        fft128_inv(x, u, tw);
        #pragma unroll
        for (int i = 0; i < 8; ++i) S[r * STRH + u + 16*i] = __float22half2_rn(x[i]);
    }
}

// Dual-row half2 inverse-row pass for k_o2 (fp16 src): 2 rows per 16-lane unit.
// WARP-UNIFORM trip counts: loop variable tb depends only on warp id, so the
// full-mask shuffles inside fft128_inv_h2 are always executed fully converged.
__device__ __forceinline__ void inv_rows_h2(
    __half2* S, const __half2* __restrict__ src, const float* __restrict__ ps, float scale,
    const __half2* __restrict__ hc, const __half2* __restrict__ hs,
    int B, int tid, int u, int hf, int w)
{
    int Bc = (B >= 64) ? 64 : B;
    int n  = (B >= 64) ? 128 : (2 * B + 1);
    int nhalf  = (n + 1) >> 1;
    int nhalfE = (nhalf + 1) & ~1;               // even bound -> warp-uniform trips
    for (int tb = 2 * w; tb < nhalfE; tb += NTS / 16) {
        int t = tb + hf;
        if (t >= nhalf) t = nhalf - 1;           // clamp (duplicate work, benign)
        int idxA = t;
        int idxB = (t + nhalf < n) ? (t + nhalf) : t;
        int rA = __brev((unsigned)((idxA - Bc) & 127)) >> 25;
        int rB = __brev((unsigned)((idxB - Bc) & 127)) >> 25;
        HC x[8];
        #pragma unroll
        for (int i = 0; i < 8; ++i) {
            int pA = rA * NN + u + 16*i;
            int pB = rB * NN + u + 16*i;
            float2 a = __half22float2(src[pA]);
            float2 bb = __half22float2(src[pB]);
            float fA = ps[pA] * scale, fB = ps[pB] * scale;
            x[i].re = __floats2half2_rn(a.x * fA, bb.x * fB);
            x[i].im = __floats2half2_rn(a.y * fA, bb.y * fB);
        }
        fft128_inv_h2(x, u, hc, hs);
        #pragma unroll
        for (int i = 0; i < 8; ++i) {
            S[rA * STRH + u + 16*i] = __lows2half2 (x[i].re, x[i].im);
            S[rB * STRH + u + 16*i] = __highs2half2(x[i].re, x[i].im);
        }
    }
    if (B < 64) {
        const __half2 hz = __float22half2_rn(make_float2(0.0f, 0.0f));
        int nz = (127 - 2 * B) * 128;
        for (int z = tid; z < nz; z += NTS) {
            int fu = B + 1 + (z >> 7);
            int a = __brev((unsigned)fu) >> 25;
            S[a * STRH + (z & 127)] = hz;
        }
    }
}

// ---------------- kernel 1: Morlet bank, pre-permuted to 2D-bitrev ----------------
__global__ void k_psi() {
    int idx = blockIdx.x * blockDim.x + threadIdx.x;
    if (idx >= NJ * NL * PLANE) return;
    int p   = idx >> 14;
    int pos = idx & (PLANE - 1);
    int R = pos >> 7, C = pos & 127;
    int r = __brev((unsigned)R) >> 25;
    int c = __brev((unsigned)C) >> 25;
    int j = p >> 2, l = p & 3;
    float fr = (float)(r < 64 ? r : r - 128) * (6.283185307179586f / 128.0f);
    float fc = (float)(c < 64 ? c : c - 128) * (6.283185307179586f / 128.0f);
    float k0    = 2.356194490192345f / (float)(1 << j);
    float sigma = 0.8f * (float)(1 << j);
    float s2    = sigma * sigma;
    float theta = 0.7853981633974483f * (float)l;
    float k0x = k0 * cosf(theta), k0y = k0 * sinf(theta);
    float beta = expf(-0.5f * s2 * k0 * k0);
    float dx = fr - k0x, dy = fc - k0y;
    float g1 = expf(-0.5f * s2 * (dx*dx + dy*dy));
    float g0 = expf(-0.5f * s2 * (fr*fr + fc*fc));
    g_psi[idx] = g1 - beta * g0;
}

// ---------------- kernel 2: fft2(image) + s0 (fp32, 64 blocks) ----------------
__global__ void __launch_bounds__(NTI, 1) k_img(const float* __restrict__ img) {
    extern __shared__ unsigned char smraw[];
    float2* S   = (float2*)smraw;
    float2* tw  = S + NN * STRIDE;
    float*  red = (float*)(tw + 128);
    int b = blockIdx.x, tid = threadIdx.x;
    int u = tid & 15, g = tid >> 4;
    if (tid < 128) {
        float s, c;
        __sincosf(-6.283185307179586f * (float)tid * (1.0f/128.0f), &s, &c);
        tw[tid] = make_float2(c, s);
    }
    __syncthreads();
    const float* ip = img + (size_t)b * PLANE;
    float lsum = 0.0f;
    #pragma unroll
    for (int iter = 0; iter < 2; ++iter) {
        int r = g + 64 * iter;
        float2 x[8];
        #pragma unroll
        for (int i = 0; i < 8; ++i) {
            float v = ip[r * NN + u + 16*i];
            lsum += v;
            x[i] = make_float2(v, 0.0f);
        }
        fft128_fwd(x, u, tw);
        #pragma unroll
        for (int i = 0; i < 8; ++i) S[r * STRIDE + u + 16*i] = x[i];
    }
    float tot = block_sum<NTI/32>(lsum, red, tid);
    if (tid == 0) g_s0[b] = tot * (1.0f / 16384.0f);
    #pragma unroll
    for (int iter = 0; iter < 2; ++iter) {
        int c = g + 64 * iter;
        float2 x[8];
        #pragma unroll
        for (int i = 0; i < 8; ++i) x[i] = S[(u + 16*i) * STRIDE + c];
        fft128_fwd(x, u, tw);
        #pragma unroll
        for (int i = 0; i < 8; ++i) S[(u + 16*i) * STRIDE + c] = x[i];
    }
    __syncthreads();
    float2* op = g_ihat + (size_t)b * PLANE;
    for (int i = tid; i < PLANE; i += NTI)
        op[i] = S[(i >> 7) * STRIDE + (i & 127)];
}

// ---------------- kernel 3: order 1 ----------------
__global__ void __launch_bounds__(NTS, 2) k_o1() {
    extern __shared__ unsigned char smraw[];
    __half2* S  = (__half2*)smraw;
    float2*  tw = (float2*)(smraw + TW_OFF);
    float*   red= (float*)(smraw + RED_OFF);
    int tid = threadIdx.x;
    int u = tid & 15, hf = (tid >> 4) & 1, w = tid >> 5;
    int rw = (w + (w & 8)) + hf * 8;
    int cw = 2 * w + hf;
    int b  = blockIdx.x >> 4;
    int j1 = (blockIdx.x >> 2) & 3;
    int l1 = blockIdx.x & 3;
    if (tid < 128) {
        float s, c;
        __sincosf(-6.283185307179586f * (float)tid * (1.0f/128.0f), &s, &c);
        tw[tid] = make_float2(c, s);
    }
    __syncthreads();
    const float2* ih = g_ihat + (size_t)b * PLANE;
    const float*  ps = g_psi + (size_t)(j1 * NL + l1) * PLANE;
    int B = BMAX[j1];
    bool produce = (j1 < 3);
    if (B >= 64) inv_rows_full(S, ih, ps, 1.0f, tw, u, rw);
    else         inv_rows_pruned(S, ih, ps, 1.0f, tw, B, tid, u, hf, w);
    __syncthreads();
    float lsum = 0.0f;
    #pragma unroll
    for (int iter = 0; iter < 4; ++iter) {          // inverse cols -> |.| (-> forward cols)
        int c = cw + 32 * iter;
        float2 x[8];
        #pragma unroll
        for (int i = 0; i < 8; ++i) x[i] = __half22float2(S[(u + 16*i) * STRH + c]);
        fft128_inv(x, u, tw);
        #pragma unroll
        for (int i = 0; i < 8; ++i) {
            float m = fast_mag(x[i]) * (1.0f / 16384.0f);
            lsum += m;
            x[i] = make_float2(m, 0.0f);
        }
        if (produce) {
            fft128_fwd(x, u, tw);
            #pragma unroll
            for (int i = 0; i < 8; ++i) S[(u + 16*i) * STRH + c] = __float22half2_rn(x[i]);
        }
    }
    float tot = block_sum<NTS/32>(lsum, red, tid);
    if (tid == 0) g_s1p[blockIdx.x] = tot;
    if (produce) {
        __half2* op = g_u1hat + (size_t)((b * 3 + j1) * NL + l1) * PLANE;
        int Bw = BMAX[j1 + 1];                      // max consumer bound
        if (Bw >= 64) {
            #pragma unroll
            for (int iter = 0; iter < 4; ++iter) {
                int r = rw + 32 * iter;
                float2 x[8];
                #pragma unroll
                for (int i = 0; i < 8; ++i) x[i] = __half22float2(S[r * STRH + u + 16*i]);
                fft128_fwd(x, u, tw);
                #pragma unroll
                for (int i = 0; i < 8; ++i) op[r * NN + u + 16*i] = __float22half2_rn(x[i]);
            }
        } else {
            int n = 2 * Bw + 1, npair = (n + 1) >> 1;
            for (int t = w; t < npair; t += NTS / 32) {
                int idx = 2 * t + hf;
                if (idx >= n) idx = n - 1;
                int kr = idx - Bw;
                int r = __brev((unsigned)(kr & 127)) >> 25;
                float2 x[8];
                #pragma unroll
                for (int i = 0; i < 8; ++i) x[i] = __half22float2(S[r * STRH + u + 16*i]);
                fft128_fwd(x, u, tw);
                #pragma unroll
                for (int i = 0; i < 8; ++i) op[r * NN + u + 16*i] = __float22half2_rn(x[i]);
            }
        }
    }
}

// ---------------- kernel 4: order 2 (dual-row + dual-column half2 passes) ----------------
__global__ void __launch_bounds__(NTS, 2) k_o2() {
    extern __shared__ unsigned char smraw[];
    __half2* S  = (__half2*)smraw;
    __half2* hc = (__half2*)(smraw + HC_OFF);
    __half2* hs = (__half2*)(smraw + HS_OFF);
    float*   red= (float*)(smraw + RED_OFF);
    int tid = threadIdx.x;
    int u = tid & 15, hf = (tid >> 4) & 1, w = tid >> 5;
    int b    = blockIdx.x / 96;
    int rem  = blockIdx.x - b * 96;
    int pair = rem >> 4;
    int l1   = (rem >> 2) & 3;
    int l2   = rem & 3;
    int j1 = PJ1[pair], j2 = PJ2[pair];
    if (tid < 128) {
        float s, c;
        __sincosf(-6.283185307179586f * (float)tid * (1.0f/128.0f), &s, &c);
        hc[tid] = __float2half2_rn(c);
        hs[tid] = __float2half2_rn(s);
    }
    __syncthreads();
    const __half2* uh = g_u1hat + (size_t)((b * 3 + j1) * NL + l1) * PLANE;
    const float*   ps = g_psi + (size_t)(j2 * NL + l2) * PLANE;
    int B = BMAX[j2];
    const float SC = 1.0f / 16384.0f;               // fold ifft norm -> fp16-safe range
    inv_rows_h2(S, uh, ps, SC, hc, hs, B, tid, u, hf, w);
    __syncthreads();
    float lsum = 0.0f;
    // dual-column inverse: warp w covers cols {4w..4w+3}; hf0 -> (4w,4w+2), hf1 -> (4w+1,4w+3)
    #pragma unroll
    for (int iter = 0; iter < 2; ++iter) {
        int c0 = 4 * w + hf + 64 * iter;
        int c1 = c0 + 2;
        HC x[8];
        #pragma unroll
        for (int i = 0; i < 8; ++i) {
            __half2 a = S[(u + 16*i) * STRH + c0];
            __half2 bb = S[(u + 16*i) * STRH + c1];
            x[i].re = __lows2half2(a, bb);
            x[i].im = __highs2half2(a, bb);
        }
        fft128_inv_h2(x, u, hc, hs);
        #pragma unroll
        for (int i = 0; i < 8; ++i) {
            float2 re = __half22float2(x[i].re);
            float2 im = __half22float2(x[i].im);
            lsum += fast_mag(make_float2(re.x, im.x));
            lsum += fast_mag(make_float2(re.y, im.y));
        }
    }
    float tot = block_sum<NTS/32>(lsum, red, tid);
    if (tid == 0) g_s2p[blockIdx.x] = tot;
}

// ---------------- kernel 5: combine + MLP ----------------
__global__ void k_head(const float* __restrict__ fc1w, const float* __restrict__ fc1b,
                       const float* __restrict__ fc2w, const float* __restrict__ fc2b,
                       float* __restrict__ out) {
    int b = blockIdx.x;
    if (threadIdx.x != 0) return;
    float coeff[11];
    coeff[0] = g_s0[b];
    #pragma unroll
    for (int j = 0; j < 4; ++j) {
        float s = 0.0f;
        #pragma unroll
        for (int l = 0; l < 4; ++l) s += g_s1p[(b * 4 + j) * 4 + l];
        coeff[1 + j] = s * (1.0f / (4.0f * 16384.0f));
    }
    #pragma unroll
    for (int p = 0; p < 6; ++p) {
        float s = 0.0f;
        #pragma unroll
        for (int k = 0; k < 16; ++k) s += g_s2p[(b * 6 + p) * 16 + k];
        coeff[5 + p] = s * (1.0f / (16.0f * 16384.0f));   // ifft norm folded into k_o2
    }
    float h[4];
    #pragma unroll
    for (int k = 0; k < 4; ++k) {
        float a = fc1b[k];
        #pragma unroll
        for (int i = 0; i < 11; ++i) a += coeff[i] * fc1w[k * 11 + i];
        h[k] = fmaxf(a, 0.0f);
    }
    #pragma unroll
    for (int o = 0; o < 10; ++o) {
        float a = fc2b[o];
        #pragma unroll
        for (int k = 0; k < 4; ++k) a += h[k] * fc2w[o * 4 + k];
        out[b * 10 + o] = 1.0f / (1.0f + expf(-a));
    }
}

// ---------------- launch ----------------
extern "C" void kernel_launch(void* const* d_in, const int* in_sizes, int n_in,
                              void* d_out, int out_size) {
    (void)in_sizes; (void)n_in; (void)out_size;
    const float* img  = (const float*)d_in[0];
    const float* fc1w = (const float*)d_in[1];
    const float* fc1b = (const float*)d_in[2];
    const float* fc2w = (const float*)d_in[3];
    const float* fc2b = (const float*)d_in[4];
    float* out = (float*)d_out;

    const size_t SMEM_IMG = (size_t)(NN * STRIDE + 128) * sizeof(float2) + (NTI / 32) * sizeof(float);
    const size_t SMEM_O   = SMEM_O_TOT;
    cudaFuncSetAttribute(k_img, cudaFuncAttributeMaxDynamicSharedMemorySize, (int)SMEM_IMG);
    cudaFuncSetAttribute(k_o1,  cudaFuncAttributeMaxDynamicSharedMemorySize, (int)SMEM_O);
    cudaFuncSetAttribute(k_o2,  cudaFuncAttributeMaxDynamicSharedMemorySize, (int)SMEM_O);

    k_psi<<<(NJ * NL * PLANE + 255) / 256, 256>>>();
    k_img<<<BATCH, NTI, SMEM_IMG>>>(img);
    k_o1 <<<BATCH * NJ * NL, NTS, SMEM_O>>>();
    k_o2 <<<BATCH * NPAIR * NL * NL, NTS, SMEM_O>>>();
    k_head<<<BATCH, 32>>>(fc1w, fc1b, fc2w, fc2b, out);
}

// round 15
// speedup vs baseline: 2.5164x; 1.0533x over previous
#include <cuda_runtime.h>
#include <cuda_fp16.h>
#include <math.h>

#define NN     128
#define PLANE  16384
#define STRIDE 129            // fp32 plane stride (k_img)
#define STRH   130            // half2 plane stride (k_o1/k_o2)
#define BATCH  64
#define NJ     4
#define NL     4
#define NPAIR  6
#define NTI    1024           // k_img threads
#define NTS    512            // k_o1/k_o2 threads (2 CTAs/SM)

#define SH_PLANE_BYTES (NN * STRH * sizeof(__half2))   // 66560
#define TW_OFF   SH_PLANE_BYTES
#define HC_OFF   (TW_OFF  + 128 * sizeof(float2))
#define HSI_OFF  (HC_OFF  + 128 * sizeof(__half2))
#define HSF_OFF  (HSI_OFF + 128 * sizeof(__half2))
#define RED_OFF  (HSF_OFF + 128 * sizeof(__half2))
#define SMEM_O_TOT (RED_OFF + (NTS / 32) * sizeof(float))

// ---------------- device scratch ----------------
static __device__ float2  g_ihat [BATCH * PLANE];                 // bitrev order, fp32
static __device__ __half2 g_u1hat[BATCH * 3 * NL * PLANE];        // bitrev, fp16, j1<3 only
static __device__ float   g_psi  [NJ * NL * PLANE];               // bitrev order
static __device__ float   g_psis [NJ * NL * PLANE];               // psi * (1/16384), fp32
static __device__ float   g_s0   [BATCH];
static __device__ float   g_s1p  [BATCH * NJ * NL];
static __device__ float   g_s2p  [BATCH * NPAIR * NL * NL];

__device__ __constant__ int PJ1[NPAIR] = {0,0,0,1,1,2};
__device__ __constant__ int PJ2[NPAIR] = {1,2,3,2,3,3};
// row-frequency support bound per scale j: |kr| <= B (k0 + 5*sigma_f). 64 = full.
__device__ __constant__ int BMAX[NJ] = {64, 64, 44, 22};

// ---------------- fp32 helpers ----------------
__device__ __forceinline__ float2 cmulf(float2 a, float2 b) {
    return make_float2(a.x*b.x - a.y*b.y, a.x*b.y + a.y*b.x);
}
__device__ __forceinline__ float2 caddf(float2 a, float2 b){ return make_float2(a.x+b.x, a.y+b.y); }
__device__ __forceinline__ float2 csubf(float2 a, float2 b){ return make_float2(a.x-b.x, a.y-b.y); }

__device__ __forceinline__ float2 shflx(float2 v, int h) {
    float2 o;
    o.x = __shfl_xor_sync(0xffffffffu, v.x, h);
    o.y = __shfl_xor_sync(0xffffffffu, v.y, h);
    return o;
}

__device__ __forceinline__ float fast_mag(float2 z) {
    float m2 = fmaf(z.x, z.x, z.y * z.y);
    float r;
    asm("sqrt.approx.f32 %0, %1;" : "=f"(r) : "f"(m2));
    return r;
}

__device__ __forceinline__ float2 ld2(const float2* p, int i)  { return p[i]; }
__device__ __forceinline__ float2 ld2(const __half2* p, int i) { return __half22float2(p[i]); }

// ---------------- half2 dual-complex helpers ----------------
struct HC { __half2 re, im; };

__device__ __forceinline__ __half2 shxh(__half2 v, int h) {
    unsigned q = __shfl_xor_sync(0xffffffffu, *reinterpret_cast<unsigned*>(&v), h);
    return *reinterpret_cast<__half2*>(&q);
}
__device__ __forceinline__ HC hcmul(HC a, __half2 wre, __half2 wim) {
    HC r;
    r.re = __hsub2(__hmul2(a.re, wre), __hmul2(a.im, wim));
    r.im = __hfma2(a.re, wim, __hmul2(a.im, wre));
    return r;
}

// ---------------- 128-pt FFT (fp32): 16 lanes x 8 regs, p = u + 16*i ----------------
__device__ __forceinline__ void fft128_fwd(float2 x[8], int u, const float2* __restrict__ tw) {
    #pragma unroll
    for (int qi = 0; qi < 2; ++qi) {
        float2 a = x[qi], b = x[qi+2], c = x[qi+4], d = x[qi+6];
        float2 t3 = caddf(a, c), t1 = csubf(a, c);
        float2 t4 = caddf(b, d), t2 = csubf(b, d);
        int j = u + 16 * qi;
        float2 w1 = tw[j], w2 = tw[2*j], w3 = tw[3*j];
        x[qi]   = caddf(t3, t4);
        x[qi+2] = cmulf(csubf(t3, t4), w2);
        x[qi+4] = cmulf(make_float2(t1.x + t2.y, t1.y - t2.x), w1);
        x[qi+6] = cmulf(make_float2(t1.x - t2.y, t1.y + t2.x), w3);
    }
    {
        float2 w = tw[u << 2];
        #pragma unroll
        for (int i = 0; i < 8; i += 2) {
            float2 a = x[i], b = x[i+1];
            x[i]   = caddf(a, b);
            x[i+1] = cmulf(csubf(a, b), w);
        }
    }
    #pragma unroll
    for (int s = 3; s < 6; ++s) {
        int h = 64 >> s;
        bool lower = (u & h) == 0;
        float sgn = lower ? 1.0f : -1.0f;
        float2 wst = tw[(u & (h - 1)) << s];
        float2 we  = lower ? make_float2(1.0f, 0.0f) : wst;
        #pragma unroll
        for (int i = 0; i < 8; ++i) {
            float2 v = x[i];
            float2 o = shflx(v, h);
            float2 t = make_float2(fmaf(sgn, v.x, o.x), fmaf(sgn, v.y, o.y));
            x[i] = cmulf(t, we);
        }
    }
    {   // s=6, h=1: twiddle == 1
        bool lower = (u & 1) == 0;
        float sgn = lower ? 1.0f : -1.0f;
        #pragma unroll
        for (int i = 0; i < 8; ++i) {
            float2 v = x[i];
            float2 o = shflx(v, 1);
            x[i] = make_float2(fmaf(sgn, v.x, o.x), fmaf(sgn, v.y, o.y));
        }
    }
}

__device__ __forceinline__ void fft128_inv(float2 x[8], int u, const float2* __restrict__ tw) {
    {   // s=6, h=1
        bool lower = (u & 1) == 0;
        float sgn = lower ? 1.0f : -1.0f;
        #pragma unroll
        for (int i = 0; i < 8; ++i) {
            float2 t = x[i];
            float2 o = shflx(t, 1);
            x[i] = make_float2(fmaf(sgn, t.x, o.x), fmaf(sgn, t.y, o.y));
        }
    }
    #pragma unroll
    for (int s = 5; s >= 3; --s) {
        int h = 64 >> s;
        bool lower = (u & h) == 0;
        float sgn = lower ? 1.0f : -1.0f;
        float2 wst = tw[(u & (h - 1)) << s];
        float2 we  = lower ? make_float2(1.0f, 0.0f) : make_float2(wst.x, -wst.y);
        #pragma unroll
        for (int i = 0; i < 8; ++i) {
            float2 t = cmulf(x[i], we);
            float2 o = shflx(t, h);
            x[i] = make_float2(fmaf(sgn, t.x, o.x), fmaf(sgn, t.y, o.y));
        }
    }
    {
        float2 w = tw[u << 2]; w.y = -w.y;
        #pragma unroll
        for (int i = 0; i < 8; i += 2) {
            float2 a = x[i], v = cmulf(x[i+1], w);
            x[i]   = caddf(a, v);
            x[i+1] = csubf(a, v);
        }
    }
    #pragma unroll
    for (int qi = 0; qi < 2; ++qi) {
        float2 a = x[qi], b = x[qi+2], c = x[qi+4], d = x[qi+6];
        int j = u + 16 * qi;
        float2 w1 = tw[j],   w2 = tw[2*j],   w3 = tw[3*j];
        w1.y = -w1.y; w2.y = -w2.y; w3.y = -w3.y;
        float2 s1 = cmulf(b, w2);
        float2 s2 = cmulf(c, w1);
        float2 s3 = cmulf(d, w3);
        float2 t3 = caddf(a, s1);
        float2 t4 = csubf(a, s1);
        float2 t1 = caddf(s2, s3);
        float2 t2 = make_float2(s3.y - s2.y, s2.x - s3.x);
        x[qi]   = caddf(t3, t1);
        x[qi+4] = csubf(t3, t1);
        x[qi+2] = caddf(t4, t2);
        x[qi+6] = csubf(t4, t2);
    }
}

// ---------------- dual inverse FFT in half2 SIMD. hsi = +sin (pre-negated) ----------------
__device__ __forceinline__ void fft128_inv_h2(HC x[8], int u,
        const __half2* __restrict__ hc, const __half2* __restrict__ hsi) {
    const __half2 ONE  = __float2half2_rn(1.0f);
    const __half2 ZERO = __float2half2_rn(0.0f);
    {   // s=6, h=1: w == 1
        __half2 sg = __float2half2_rn(((u & 1) == 0) ? 1.0f : -1.0f);
        #pragma unroll
        for (int i = 0; i < 8; ++i) {
            __half2 orr = shxh(x[i].re, 1), oii = shxh(x[i].im, 1);
            x[i].re = __hfma2(sg, x[i].re, orr);
            x[i].im = __hfma2(sg, x[i].im, oii);
        }
    }
    #pragma unroll
    for (int s = 5; s >= 3; --s) {
        int h = 64 >> s;
        bool lower = (u & h) == 0;
        __half2 sg = __float2half2_rn(lower ? 1.0f : -1.0f);
        int k = (u & (h - 1)) << s;
        __half2 wre = lower ? ONE  : hc[k];
        __half2 wim = lower ? ZERO : hsi[k];
        #pragma unroll
        for (int i = 0; i < 8; ++i) {
            HC t = hcmul(x[i], wre, wim);
            __half2 orr = shxh(t.re, h), oii = shxh(t.im, h);
            x[i].re = __hfma2(sg, t.re, orr);
            x[i].im = __hfma2(sg, t.im, oii);
        }
    }
    {   // m=16 stage
        __half2 wre = hc[u << 2], wim = hsi[u << 2];
        #pragma unroll
        for (int i = 0; i < 8; i += 2) {
            HC v = hcmul(x[i+1], wre, wim);
            HC a = x[i];
            x[i].re   = __hadd2(a.re, v.re);  x[i].im   = __hadd2(a.im, v.im);
            x[i+1].re = __hsub2(a.re, v.re);  x[i+1].im = __hsub2(a.im, v.im);
        }
    }
    #pragma unroll
    for (int qi = 0; qi < 2; ++qi) {
        int j = u + 16 * qi;
        __half2 w1re = hc[j],   w1im = hsi[j];
        __half2 w2re = hc[2*j], w2im = hsi[2*j];
        __half2 w3re = hc[3*j], w3im = hsi[3*j];
        HC a = x[qi], b = x[qi+2], c = x[qi+4], d = x[qi+6];
        HC s1 = hcmul(b, w2re, w2im);
        HC s2 = hcmul(c, w1re, w1im);
        HC s3 = hcmul(d, w3re, w3im);
        HC t3, t4, t1, t2;
        t3.re = __hadd2(a.re, s1.re);  t3.im = __hadd2(a.im, s1.im);
        t4.re = __hsub2(a.re, s1.re);  t4.im = __hsub2(a.im, s1.im);
        t1.re = __hadd2(s2.re, s3.re); t1.im = __hadd2(s2.im, s3.im);
        t2.re = __hsub2(s3.im, s2.im); t2.im = __hsub2(s2.re, s3.re);
        x[qi].re   = __hadd2(t3.re, t1.re); x[qi].im   = __hadd2(t3.im, t1.im);
        x[qi+4].re = __hsub2(t3.re, t1.re); x[qi+4].im = __hsub2(t3.im, t1.im);
        x[qi+2].re = __hadd2(t4.re, t2.re); x[qi+2].im = __hadd2(t4.im, t2.im);
        x[qi+6].re = __hsub2(t4.re, t2.re); x[qi+6].im = __hsub2(t4.im, t2.im);
    }
}

// ---------------- dual forward FFT in half2 SIMD. hsf = -sin (fwd twiddle imag) ----------------
__device__ __forceinline__ void fft128_fwd_h2(HC x[8], int u,
        const __half2* __restrict__ hc, const __half2* __restrict__ hsf) {
    const __half2 ONE  = __float2half2_rn(1.0f);
    const __half2 ZERO = __float2half2_rn(0.0f);
    #pragma unroll
    for (int qi = 0; qi < 2; ++qi) {
        HC a = x[qi], b = x[qi+2], c = x[qi+4], d = x[qi+6];
        HC t3, t1, t4, t2;
        t3.re = __hadd2(a.re, c.re); t3.im = __hadd2(a.im, c.im);
        t1.re = __hsub2(a.re, c.re); t1.im = __hsub2(a.im, c.im);
        t4.re = __hadd2(b.re, d.re); t4.im = __hadd2(b.im, d.im);
        t2.re = __hsub2(b.re, d.re); t2.im = __hsub2(b.im, d.im);
        int j = u + 16 * qi;
        __half2 w1re = hc[j],   w1im = hsf[j];
        __half2 w2re = hc[2*j], w2im = hsf[2*j];
        __half2 w3re = hc[3*j], w3im = hsf[3*j];
        x[qi].re = __hadd2(t3.re, t4.re); x[qi].im = __hadd2(t3.im, t4.im);
        HC d2; d2.re = __hsub2(t3.re, t4.re); d2.im = __hsub2(t3.im, t4.im);
        x[qi+2] = hcmul(d2, w2re, w2im);
        HC p; p.re = __hadd2(t1.re, t2.im); p.im = __hsub2(t1.im, t2.re);
        x[qi+4] = hcmul(p, w1re, w1im);
        HC q; q.re = __hsub2(t1.re, t2.im); q.im = __hadd2(t1.im, t2.re);
        x[qi+6] = hcmul(q, w3re, w3im);
    }
    {
        __half2 wre = hc[u << 2], wim = hsf[u << 2];
        #pragma unroll
        for (int i = 0; i < 8; i += 2) {
            HC a = x[i], b = x[i+1];
            x[i].re = __hadd2(a.re, b.re); x[i].im = __hadd2(a.im, b.im);
            HC d2; d2.re = __hsub2(a.re, b.re); d2.im = __hsub2(a.im, b.im);
            x[i+1] = hcmul(d2, wre, wim);
        }
    }
    #pragma unroll
    for (int s = 3; s < 6; ++s) {
        int h = 64 >> s;
        bool lower = (u & h) == 0;
        __half2 sg = __float2half2_rn(lower ? 1.0f : -1.0f);
        int k = (u & (h - 1)) << s;
        __half2 wre = lower ? ONE  : hc[k];
        __half2 wim = lower ? ZERO : hsf[k];
        #pragma unroll
        for (int i = 0; i < 8; ++i) {
            __half2 orr = shxh(x[i].re, h), oii = shxh(x[i].im, h);
            HC t; t.re = __hfma2(sg, x[i].re, orr); t.im = __hfma2(sg, x[i].im, oii);
            x[i] = hcmul(t, wre, wim);
        }
    }
    {   // s=6, twiddle == 1
        __half2 sg = __float2half2_rn(((u & 1) == 0) ? 1.0f : -1.0f);
        #pragma unroll
        for (int i = 0; i < 8; ++i) {
            __half2 orr = shxh(x[i].re, 1), oii = shxh(x[i].im, 1);
            x[i].re = __hfma2(sg, x[i].re, orr);
            x[i].im = __hfma2(sg, x[i].im, oii);
        }
    }
}

// Deterministic block reduction; valid on tid==0. One __syncthreads inside.
template<int NWARPS>
__device__ __forceinline__ float block_sum(float v, float* red, int tid) {
    #pragma unroll
    for (int o = 16; o > 0; o >>= 1) v += __shfl_down_sync(0xffffffffu, v, o);
    if ((tid & 31) == 0) red[tid >> 5] = v;
    __syncthreads();
    float total = 0.0f;
    if (tid == 0) {
        #pragma unroll
        for (int w = 0; w < NWARPS; ++w) total += red[w];
    }
    return total;
}

// Pruned inverse-row pass (fp32 FFT), zero-fill the rest. Used by k_o1.
template<typename SRC>
__device__ __forceinline__ void inv_rows_pruned(
    __half2* S, const SRC* __restrict__ src, const float* __restrict__ ps,
    const float2* __restrict__ tw, int B, int tid, int u, int hf, int w)
{
    int n = 2 * B + 1;
    int npair = (n + 1) >> 1;
    for (int t = w; t < npair; t += NTS / 32) {
        int idx = 2 * t + hf;
        if (idx >= n) idx = n - 1;
        int kr = idx - B;
        int r = __brev((unsigned)(kr & 127)) >> 25;
        float2 x[8];
        #pragma unroll
        for (int i = 0; i < 8; ++i) {
            int p = r * NN + u + 16*i;
            float2 v = ld2(src, p);
            float  f = ps[p];
            x[i] = make_float2(v.x * f, v.y * f);
        }
        fft128_inv(x, u, tw);
        #pragma unroll
        for (int i = 0; i < 8; ++i) S[r * STRH + u + 16*i] = __float22half2_rn(x[i]);
    }
    const __half2 hz = __float22half2_rn(make_float2(0.0f, 0.0f));
    int nz = (127 - 2 * B) * 128;
    for (int z = tid; z < nz; z += NTS) {
        int fu = B + 1 + (z >> 7);
        int a = __brev((unsigned)fu) >> 25;
        S[a * STRH + (z & 127)] = hz;
    }
}

template<typename SRC>
__device__ __forceinline__ void inv_rows_full(
    __half2* S, const SRC* __restrict__ src, const float* __restrict__ ps,
    const float2* __restrict__ tw, int u, int rw)
{
    #pragma unroll
    for (int iter = 0; iter < 4; ++iter) {
        int r = rw + 32 * iter;
        float2 x[8];
        #pragma unroll
        for (int i = 0; i < 8; ++i) {
            int p = r * NN + u + 16*i;
            float2 v = ld2(src, p);
            float  f = ps[p];
            x[i] = make_float2(v.x * f, v.y * f);
        }
        fft128_inv(x, u, tw);
        #pragma unroll
        for (int i = 0; i < 8; ++i) S[r * STRH + u + 16*i] = __float22half2_rn(x[i]);
    }
}

// Dual-row half2 inverse-row pass for k_o2 (fp16 src, pre-scaled fp32 psi).
// WARP-UNIFORM trip counts (tb depends only on warp id).
__device__ __forceinline__ void inv_rows_h2(
    __half2* S, const __half2* __restrict__ src, const float* __restrict__ ps,
    const __half2* __restrict__ hc, const __half2* __restrict__ hsi,
    int B, int tid, int u, int hf, int w)
{
    int Bc = (B >= 64) ? 64 : B;
    int n  = (B >= 64) ? 128 : (2 * B + 1);
    int nhalf  = (n + 1) >> 1;
    int nhalfE = (nhalf + 1) & ~1;
    for (int tb = 2 * w; tb < nhalfE; tb += NTS / 16) {
        int t = tb + hf;
        if (t >= nhalf) t = nhalf - 1;           // clamp (duplicate work, benign)
        int idxA = t;
        int idxB = (t + nhalf < n) ? (t + nhalf) : t;
        int rA = __brev((unsigned)((idxA - Bc) & 127)) >> 25;
        int rB = __brev((unsigned)((idxB - Bc) & 127)) >> 25;
        HC x[8];
        #pragma unroll
        for (int i = 0; i < 8; ++i) {
            int pA = rA * NN + u + 16*i;
            int pB = rB * NN + u + 16*i;
            float2 a = __half22float2(src[pA]);
            float2 bb = __half22float2(src[pB]);
            float fA = ps[pA], fB = ps[pB];
            x[i].re = __floats2half2_rn(a.x * fA, bb.x * fB);
            x[i].im = __floats2half2_rn(a.y * fA, bb.y * fB);
        }
        fft128_inv_h2(x, u, hc, hsi);
        #pragma unroll
        for (int i = 0; i < 8; ++i) {
            S[rA * STRH + u + 16*i] = __lows2half2 (x[i].re, x[i].im);
            S[rB * STRH + u + 16*i] = __highs2half2(x[i].re, x[i].im);
        }
    }
    if (B < 64) {
        const __half2 hz = __float22half2_rn(make_float2(0.0f, 0.0f));
        int nz = (127 - 2 * B) * 128;
        for (int z = tid; z < nz; z += NTS) {
            int fu = B + 1 + (z >> 7);
            int a = __brev((unsigned)fu) >> 25;
            S[a * STRH + (z & 127)] = hz;
        }
    }
}

// ---------------- kernel 1: Morlet bank, pre-permuted to 2D-bitrev ----------------
__global__ void k_psi() {
    int idx = blockIdx.x * blockDim.x + threadIdx.x;
    if (idx >= NJ * NL * PLANE) return;
    int p   = idx >> 14;
    int pos = idx & (PLANE - 1);
    int R = pos >> 7, C = pos & 127;
    int r = __brev((unsigned)R) >> 25;
    int c = __brev((unsigned)C) >> 25;
    int j = p >> 2, l = p & 3;
    float fr = (float)(r < 64 ? r : r - 128) * (6.283185307179586f / 128.0f);
    float fc = (float)(c < 64 ? c : c - 128) * (6.283185307179586f / 128.0f);
    float k0    = 2.356194490192345f / (float)(1 << j);
    float sigma = 0.8f * (float)(1 << j);
    float s2    = sigma * sigma;
    float theta = 0.7853981633974483f * (float)l;
    float k0x = k0 * cosf(theta), k0y = k0 * sinf(theta);
    float beta = expf(-0.5f * s2 * k0 * k0);
    float dx = fr - k0x, dy = fc - k0y;
    float g1 = expf(-0.5f * s2 * (dx*dx + dy*dy));
    float g0 = expf(-0.5f * s2 * (fr*fr + fc*fc));
    float v = g1 - beta * g0;
    g_psi [idx] = v;
    g_psis[idx] = v * (1.0f / 16384.0f);
}

// ---------------- kernel 2: fft2(image) + s0 (fp32, 64 blocks) ----------------
__global__ void __launch_bounds__(NTI, 1) k_img(const float* __restrict__ img) {
    extern __shared__ unsigned char smraw[];
    float2* S   = (float2*)smraw;
    float2* tw  = S + NN * STRIDE;
    float*  red = (float*)(tw + 128);
    int b = blockIdx.x, tid = threadIdx.x;
    int u = tid & 15, g = tid >> 4;
    if (tid < 128) {
        float s, c;
        __sincosf(-6.283185307179586f * (float)tid * (1.0f/128.0f), &s, &c);
        tw[tid] = make_float2(c, s);
    }
    __syncthreads();
    const float* ip = img + (size_t)b * PLANE;
    float lsum = 0.0f;
    #pragma unroll
    for (int iter = 0; iter < 2; ++iter) {
        int r = g + 64 * iter;
        float2 x[8];
        #pragma unroll
        for (int i = 0; i < 8; ++i) {
            float v = ip[r * NN + u + 16*i];
            lsum += v;
            x[i] = make_float2(v, 0.0f);
        }
        fft128_fwd(x, u, tw);
        #pragma unroll
        for (int i = 0; i < 8; ++i) S[r * STRIDE + u + 16*i] = x[i];
    }
    float tot = block_sum<NTI/32>(lsum, red, tid);
    if (tid == 0) g_s0[b] = tot * (1.0f / 16384.0f);
    #pragma unroll
    for (int iter = 0; iter < 2; ++iter) {
        int c = g + 64 * iter;
        float2 x[8];
        #pragma unroll
        for (int i = 0; i < 8; ++i) x[i] = S[(u + 16*i) * STRIDE + c];
        fft128_fwd(x, u, tw);
        #pragma unroll
        for (int i = 0; i < 8; ++i) S[(u + 16*i) * STRIDE + c] = x[i];
    }
    __syncthreads();
    float2* op = g_ihat + (size_t)b * PLANE;
    for (int i = tid; i < PLANE; i += NTI)
        op[i] = S[(i >> 7) * STRIDE + (i & 127)];
}

// ---------------- kernel 3: order 1 (dual-column half2 col pass) ----------------
__global__ void __launch_bounds__(NTS, 2) k_o1() {
    extern __shared__ unsigned char smraw[];
    __half2* S   = (__half2*)smraw;
    float2*  tw  = (float2*)(smraw + TW_OFF);
    __half2* hc  = (__half2*)(smraw + HC_OFF);
    __half2* hsi = (__half2*)(smraw + HSI_OFF);
    __half2* hsf = (__half2*)(smraw + HSF_OFF);
    float*   red = (float*)(smraw + RED_OFF);
    int tid = threadIdx.x;
    int u = tid & 15, hf = (tid >> 4) & 1, w = tid >> 5;
    int rw = (w + (w & 8)) + hf * 8;
    int b  = blockIdx.x >> 4;
    int j1 = (blockIdx.x >> 2) & 3;
    int l1 = blockIdx.x & 3;
    if (tid < 128) {
        float s, c;
        __sincosf(-6.283185307179586f * (float)tid * (1.0f/128.0f), &s, &c);
        tw[tid]  = make_float2(c, s);
        hc[tid]  = __float2half2_rn(c);
        hsf[tid] = __float2half2_rn(s);
        hsi[tid] = __float2half2_rn(-s);
    }
    __syncthreads();
    const float2* ih = g_ihat + (size_t)b * PLANE;
    const float*  ps = g_psi + (size_t)(j1 * NL + l1) * PLANE;
    int B = BMAX[j1];
    bool produce = (j1 < 3);
    if (B >= 64) inv_rows_full(S, ih, ps, tw, u, rw);
    else         inv_rows_pruned(S, ih, ps, tw, B, tid, u, hf, w);
    __syncthreads();
    float lsum = 0.0f;
    // dual-column: warp w covers cols {4w..4w+3}; hf0 -> (4w,4w+2), hf1 -> (4w+1,4w+3)
    #pragma unroll
    for (int iter = 0; iter < 2; ++iter) {
        int c0 = 4 * w + hf + 64 * iter;
        int c1 = c0 + 2;
        HC x[8];
        #pragma unroll
        for (int i = 0; i < 8; ++i) {
            __half2 a = S[(u + 16*i) * STRH + c0];
            __half2 bb = S[(u + 16*i) * STRH + c1];
            x[i].re = __lows2half2(a, bb);
            x[i].im = __highs2half2(a, bb);
        }
        fft128_inv_h2(x, u, hc, hsi);
        #pragma unroll
        for (int i = 0; i < 8; ++i) {
            float2 re = __half22float2(x[i].re);
            float2 im = __half22float2(x[i].im);
            float mA = fast_mag(make_float2(re.x, im.x)) * (1.0f / 16384.0f);
            float mB = fast_mag(make_float2(re.y, im.y)) * (1.0f / 16384.0f);
            lsum += mA + mB;
            x[i].re = __floats2half2_rn(mA, mB);
            x[i].im = __float2half2_rn(0.0f);
        }
        if (produce) {
            fft128_fwd_h2(x, u, hc, hsf);
            #pragma unroll
            for (int i = 0; i < 8; ++i) {
                S[(u + 16*i) * STRH + c0] = __lows2half2 (x[i].re, x[i].im);
                S[(u + 16*i) * STRH + c1] = __highs2half2(x[i].re, x[i].im);
            }
        }
    }
    float tot = block_sum<NTS/32>(lsum, red, tid);   // sync orders S stores
    if (tid == 0) g_s1p[blockIdx.x] = tot;
    if (produce) {
        __half2* op = g_u1hat + (size_t)((b * 3 + j1) * NL + l1) * PLANE;
        int Bw = BMAX[j1 + 1];                      // max consumer bound
        if (Bw >= 64) {
            #pragma unroll
            for (int iter = 0; iter < 4; ++iter) {
                int r = rw + 32 * iter;
                float2 x[8];
                #pragma unroll
                for (int i = 0; i < 8; ++i) x[i] = __half22float2(S[r * STRH + u + 16*i]);
                fft128_fwd(x, u, tw);
                #pragma unroll
                for (int i = 0; i < 8; ++i) op[r * NN + u + 16*i] = __float22half2_rn(x[i]);
            }
        } else {
            int n = 2 * Bw + 1, npair = (n + 1) >> 1;
            for (int t = w; t < npair; t += NTS / 32) {
                int idx = 2 * t + hf;
                if (idx >= n) idx = n - 1;
                int kr = idx - Bw;
                int r = __brev((unsigned)(kr & 127)) >> 25;
                float2 x[8];
                #pragma unroll
                for (int i = 0; i < 8; ++i) x[i] = __half22float2(S[r * STRH + u + 16*i]);
                fft128_fwd(x, u, tw);
                #pragma unroll
                for (int i = 0; i < 8; ++i) op[r * NN + u + 16*i] = __float22half2_rn(x[i]);
            }
        }
    }
}

// ---------------- kernel 4: order 2 (dual-row + dual-column half2 passes) ----------------
__global__ void __launch_bounds__(NTS, 2) k_o2() {
    extern __shared__ unsigned char smraw[];
    __half2* S   = (__half2*)smraw;
    __half2* hc  = (__half2*)(smraw + HC_OFF);
    __half2* hsi = (__half2*)(smraw + HSI_OFF);
    float*   red = (float*)(smraw + RED_OFF);
    int tid = threadIdx.x;
    int u = tid & 15, hf = (tid >> 4) & 1, w = tid >> 5;
    int b    = blockIdx.x / 96;
    int rem  = blockIdx.x - b * 96;
    int pair = rem >> 4;
    int l1   = (rem >> 2) & 3;
    int l2   = rem & 3;
    int j1 = PJ1[pair], j2 = PJ2[pair];
    if (tid < 128) {
        float s, c;
        __sincosf(-6.283185307179586f * (float)tid * (1.0f/128.0f), &s, &c);
        hc[tid]  = __float2half2_rn(c);
        hsi[tid] = __float2half2_rn(-s);
    }
    __syncthreads();
    const __half2* uh = g_u1hat + (size_t)((b * 3 + j1) * NL + l1) * PLANE;
    const float*   ps = g_psis + (size_t)(j2 * NL + l2) * PLANE;   // pre-scaled psi/16384
    int B = BMAX[j2];
    inv_rows_h2(S, uh, ps, hc, hsi, B, tid, u, hf, w);
    __syncthreads();
    float lsum = 0.0f;
    #pragma unroll
    for (int iter = 0; iter < 2; ++iter) {
        int c0 = 4 * w + hf + 64 * iter;
        int c1 = c0 + 2;
        HC x[8];
        #pragma unroll
        for (int i = 0; i < 8; ++i) {
            __half2 a = S[(u + 16*i) * STRH + c0];
            __half2 bb = S[(u + 16*i) * STRH + c1];
            x[i].re = __lows2half2(a, bb);
            x[i].im = __highs2half2(a, bb);
        }
        fft128_inv_h2(x, u, hc, hsi);
        #pragma unroll
        for (int i = 0; i < 8; ++i) {
            float2 re = __half22float2(x[i].re);
            float2 im = __half22float2(x[i].im);
            lsum += fast_mag(make_float2(re.x, im.x));
            lsum += fast_mag(make_float2(re.y, im.y));
        }
    }
    float tot = block_sum<NTS/32>(lsum, red, tid);
    if (tid == 0) g_s2p[blockIdx.x] = tot;
}

// ---------------- kernel 5: combine + MLP ----------------
__global__ void k_head(const float* __restrict__ fc1w, const float* __restrict__ fc1b,
                       const float* __restrict__ fc2w, const float* __restrict__ fc2b,
                       float* __restrict__ out) {
    int b = blockIdx.x;
    if (threadIdx.x != 0) return;
    float coeff[11];
    coeff[0] = g_s0[b];
    #pragma unroll
    for (int j = 0; j < 4; ++j) {
        float s = 0.0f;
        #pragma unroll
        for (int l = 0; l < 4; ++l) s += g_s1p[(b * 4 + j) * 4 + l];
        coeff[1 + j] = s * (1.0f / (4.0f * 16384.0f));
    }
    #pragma unroll
    for (int p = 0; p < 6; ++p) {
        float s = 0.0f;
        #pragma unroll
        for (int k = 0; k < 16; ++k) s += g_s2p[(b * 6 + p) * 16 + k];
        coeff[5 + p] = s * (1.0f / (16.0f * 16384.0f));   // ifft norm folded via g_psis
    }
    float h[4];
    #pragma unroll
    for (int k = 0; k < 4; ++k) {
        float a = fc1b[k];
        #pragma unroll
        for (int i = 0; i < 11; ++i) a += coeff[i] * fc1w[k * 11 + i];
        h[k] = fmaxf(a, 0.0f);
    }
    #pragma unroll
    for (int o = 0; o < 10; ++o) {
        float a = fc2b[o];
        #pragma unroll
        for (int k = 0; k < 4; ++k) a += h[k] * fc2w[o * 4 + k];
        out[b * 10 + o] = 1.0f / (1.0f + expf(-a));
    }
}

// ---------------- launch ----------------
extern "C" void kernel_launch(void* const* d_in, const int* in_sizes, int n_in,
                              void* d_out, int out_size) {
    (void)in_sizes; (void)n_in; (void)out_size;
    const float* img  = (const float*)d_in[0];
    const float* fc1w = (const float*)d_in[1];
    const float* fc1b = (const float*)d_in[2];
    const float* fc2w = (const float*)d_in[3];
    const float* fc2b = (const float*)d_in[4];
    float* out = (float*)d_out;

    const size_t SMEM_IMG = (size_t)(NN * STRIDE + 128) * sizeof(float2) + (NTI / 32) * sizeof(float);
    const size_t SMEM_O   = SMEM_O_TOT;
    cudaFuncSetAttribute(k_img, cudaFuncAttributeMaxDynamicSharedMemorySize, (int)SMEM_IMG);
    cudaFuncSetAttribute(k_o1,  cudaFuncAttributeMaxDynamicSharedMemorySize, (int)SMEM_O);
    cudaFuncSetAttribute(k_o2,  cudaFuncAttributeMaxDynamicSharedMemorySize, (int)SMEM_O);

    k_psi<<<(NJ * NL * PLANE + 255) / 256, 256>>>();
    k_img<<<BATCH, NTI, SMEM_IMG>>>(img);
    k_o1 <<<BATCH * NJ * NL, NTS, SMEM_O>>>();
    k_o2 <<<BATCH * NPAIR * NL * NL, NTS, SMEM_O>>>();
    k_head<<<BATCH, 32>>>(fc1w, fc1b, fc2w, fc2b, out);
}